// round 3
// baseline (speedup 1.0000x reference)
#include <cuda_runtime.h>
#include <math.h>

// Problem constants
#define Bx    64
#define Tt    2048
#define HIDx  1024
#define ENCx  512
#define Ux    256
#define FILTx 32
#define KWx   31

// GEMM tiling
#define BM 64
#define BN 256
#define BK 32
#define NTILES (Tt / BM)   // 32

// ---------------- scratch (device globals; no allocation allowed) ----------------
__device__ float g_Wme[ENCx * Ux];                    // Wm @ We
__device__ float g_Wle[FILTx * Ux];                   // Wl @ We
__device__ float g_pqe[Bx * Ux];                      // (pq_full + bl + bm) @ We + be
__device__ float g_f[(size_t)Bx * FILTx * Tt];        // conv output
__device__ float g_pA[Bx * NTILES * ENCx];            // sum_t state*mem (per tile)
__device__ float g_pB[Bx * NTILES * ENCx];            // sum_t s*mem (per tile)
__device__ float g_pS[Bx * NTILES];                   // sum_t s (per tile)
__device__ float g_pSt[Bx * NTILES];                  // sum_t state (per tile)

// ---------------- setup: weight folding Wme = Wm@We, Wle = Wl@We ----------------
__global__ void k_wfold(const float* __restrict__ Wm, const float* __restrict__ Wl,
                        const float* __restrict__ We) {
    int r = blockIdx.x;
    int u = threadIdx.x;   // 256 threads
    float a = 0.f;
    if (r < ENCx) {
        const float* wrow = Wm + r * Ux;
        #pragma unroll 4
        for (int v = 0; v < Ux; ++v) a = fmaf(wrow[v], We[v * Ux + u], a);
        g_Wme[r * Ux + u] = a;
    } else {
        int fr = r - ENCx;
        const float* wrow = Wl + fr * Ux;
        #pragma unroll 4
        for (int v = 0; v < Ux; ++v) a = fmaf(wrow[v], We[v * Ux + u], a);
        g_Wle[fr * Ux + u] = a;
    }
}

// ---------------- setup: per-batch fused bias vector pqe ----------------
// pqe[b,:] = (query[b,1,:]@Wq + bq + bl + bm) @ We + be
__global__ void k_pqe(const float* __restrict__ query, const float* __restrict__ Wq,
                      const float* __restrict__ bq, const float* __restrict__ bl,
                      const float* __restrict__ bm, const float* __restrict__ We,
                      const float* __restrict__ be) {
    __shared__ float tmp[Ux];
    int b = blockIdx.x, tid = threadIdx.x;  // 256 threads
    const float* q = query + ((size_t)b * 2 + 1) * HIDx;  // query[:,1,:]
    float a = bq[tid] + bl[tid] + bm[tid];
    #pragma unroll 4
    for (int h = 0; h < HIDx; ++h) a = fmaf(q[h], Wq[h * Ux + tid], a);
    tmp[tid] = a;
    __syncthreads();
    float c = be[tid];
    #pragma unroll 4
    for (int v = 0; v < Ux; ++v) c = fmaf(tmp[v], We[v * Ux + tid], c);
    g_pqe[b * Ux + tid] = c;
}

// ---------------- setup: SAME conv over state, f[b,32,T] ----------------
__global__ void k_conv(const float* __restrict__ state, const float* __restrict__ conv_w,
                       const float* __restrict__ conv_b) {
    __shared__ float xs[Tt + KWx - 1];
    __shared__ float ws[FILTx * KWx];
    int b = blockIdx.x, tid = threadIdx.x, nth = blockDim.x;
    for (int i = tid; i < Tt + KWx - 1; i += nth) {
        int t = i - (KWx - 1) / 2;
        xs[i] = (t >= 0 && t < Tt) ? state[b * Tt + t] : 0.f;
    }
    for (int i = tid; i < FILTx * KWx; i += nth) ws[i] = conv_w[i];
    __syncthreads();
    for (int f = 0; f < FILTx; ++f) {
        float cb = conv_b[f];
        const float* wf = &ws[f * KWx];
        for (int t = tid; t < Tt; t += nth) {
            float a = cb;
            #pragma unroll
            for (int k = 0; k < KWx; ++k) a = fmaf(wf[k], xs[t + k], a);
            g_f[((size_t)b * FILTx + f) * Tt + t] = a;
        }
    }
}

// ---------------- main fused kernel ----------------
// Per block: (b, t-tile of 64 rows). Compute z[64,256] = mem@Wme + f@Wle,
// add pqe, tanh, dot v_a -> energy, sigmoid -> s; accumulate weighted memory
// sums (state-weighted and s-weighted) into per-tile scratch slots.
__global__ __launch_bounds__(256, 2)
void k_main(const float* __restrict__ memory, const float* __restrict__ state,
            const float* __restrict__ v_a) {
    const int b    = blockIdx.x >> 5;       // / NTILES
    const int tile = blockIdx.x & 31;       // % NTILES
    const int t0   = tile * BM;

    __shared__ float As[BK][BM + 4];        // A tile transposed [k][m]
    __shared__ float Bsm[BK][BN];           // B tile [k][n]
    __shared__ float s_sm[BM];
    __shared__ float st_sm[BM];

    const int tid = threadIdx.x;
    const int tx  = tid & 31;               // N direction (32)
    const int ty  = tid >> 5;               // M direction (8)

    if (tid < BM) st_sm[tid] = state[b * Tt + t0 + tid];

    float acc[8][8];
    #pragma unroll
    for (int i = 0; i < 8; ++i)
        #pragma unroll
        for (int j = 0; j < 8; ++j) acc[i][j] = 0.f;

    const float* memb = memory + ((size_t)b * Tt + t0) * ENCx;

    // 16 K-tiles from memory/Wme + 1 K-tile from f/Wle (FILT == 32 == BK)
    for (int kt = 0; kt <= ENCx / BK; ++kt) {
        __syncthreads();
        if (kt < ENCx / BK) {
            int e0 = kt * BK;
            #pragma unroll
            for (int p = 0; p < 8; ++p) {   // 2048 floats of A
                int idx = p * 256 + tid;
                int k = idx & 31, m = idx >> 5;
                As[k][m] = memb[(size_t)m * ENCx + e0 + k];
            }
            #pragma unroll
            for (int p = 0; p < 8; ++p) {   // 8192 floats of B as float4
                int idx = p * 256 + tid;
                int k = idx >> 6, n4 = idx & 63;
                *(float4*)&Bsm[k][n4 * 4] = *(const float4*)&g_Wme[(size_t)(e0 + k) * BN + n4 * 4];
            }
        } else {
            #pragma unroll
            for (int p = 0; p < 8; ++p) {
                int idx = p * 256 + tid;
                int m = idx & 63, f = idx >> 6;
                As[f][m] = g_f[((size_t)b * FILTx + f) * Tt + t0 + m];
            }
            #pragma unroll
            for (int p = 0; p < 8; ++p) {
                int idx = p * 256 + tid;
                int k = idx >> 6, n4 = idx & 63;
                *(float4*)&Bsm[k][n4 * 4] = *(const float4*)&g_Wle[(size_t)k * BN + n4 * 4];
            }
        }
        __syncthreads();
        #pragma unroll
        for (int k = 0; k < BK; ++k) {
            float a[8], bb[8];
            float4 a0 = *(const float4*)&As[k][ty * 4];
            float4 a1 = *(const float4*)&As[k][32 + ty * 4];
            float4 b0 = *(const float4*)&Bsm[k][tx * 4];
            float4 b1 = *(const float4*)&Bsm[k][128 + tx * 4];
            a[0] = a0.x; a[1] = a0.y; a[2] = a0.z; a[3] = a0.w;
            a[4] = a1.x; a[5] = a1.y; a[6] = a1.z; a[7] = a1.w;
            bb[0] = b0.x; bb[1] = b0.y; bb[2] = b0.z; bb[3] = b0.w;
            bb[4] = b1.x; bb[5] = b1.y; bb[6] = b1.z; bb[7] = b1.w;
            #pragma unroll
            for (int i = 0; i < 8; ++i)
                #pragma unroll
                for (int j = 0; j < 8; ++j)
                    acc[i][j] = fmaf(a[i], bb[j], acc[i][j]);
        }
    }

    // ---- epilogue: tanh, v_a dot, sigmoid ----
    const float* pqe_b = g_pqe + b * Ux;
    float pq[8], va[8];
    #pragma unroll
    for (int j = 0; j < 4; ++j) {
        pq[j]     = pqe_b[tx * 4 + j];        va[j]     = v_a[tx * 4 + j];
        pq[4 + j] = pqe_b[128 + tx * 4 + j];  va[4 + j] = v_a[128 + tx * 4 + j];
    }
    float ep[8];
    #pragma unroll
    for (int i = 0; i < 8; ++i) {
        float e = 0.f;
        #pragma unroll
        for (int j = 0; j < 8; ++j)
            e = fmaf(va[j], tanhf(acc[i][j] + pq[j]), e);
        ep[i] = e;
    }
    #pragma unroll
    for (int off = 16; off > 0; off >>= 1)
        #pragma unroll
        for (int i = 0; i < 8; ++i)
            ep[i] += __shfl_xor_sync(0xffffffffu, ep[i], off);
    if (tx == 0) {
        #pragma unroll
        for (int i = 0; i < 4; ++i) s_sm[ty * 4 + i]      = 1.f / (1.f + expf(-ep[i]));
        #pragma unroll
        for (int i = 0; i < 4; ++i) s_sm[32 + ty * 4 + i] = 1.f / (1.f + expf(-ep[4 + i]));
    }
    __syncthreads();

    // block-level sums of s and state (deterministic, no atomics)
    if (tid < 32) {
        float S  = s_sm[tid]  + s_sm[tid + 32];
        float St = st_sm[tid] + st_sm[tid + 32];
        #pragma unroll
        for (int off = 16; off > 0; off >>= 1) {
            S  += __shfl_xor_sync(0xffffffffu, S, off);
            St += __shfl_xor_sync(0xffffffffu, St, off);
        }
        if (tid == 0) {
            g_pS[b * NTILES + tile]  = S;
            g_pSt[b * NTILES + tile] = St;
        }
    }

    // ---- weighted memory sums over this tile (memory tile is L2-hot) ----
    float aA0 = 0.f, aB0 = 0.f, aA1 = 0.f, aB1 = 0.f;
    const float* p0 = memb + tid;
    const float* p1 = memb + tid + 256;
    #pragma unroll 4
    for (int m = 0; m < BM; ++m) {
        float v0 = p0[(size_t)m * ENCx];
        float v1 = p1[(size_t)m * ENCx];
        float sw  = s_sm[m];
        float stw = st_sm[m];
        aA0 = fmaf(stw, v0, aA0);  aB0 = fmaf(sw, v0, aB0);
        aA1 = fmaf(stw, v1, aA1);  aB1 = fmaf(sw, v1, aB1);
    }
    int base = (b * NTILES + tile) * ENCx;
    g_pA[base + tid]       = aA0;
    g_pA[base + tid + 256] = aA1;
    g_pB[base + tid]       = aB0;
    g_pB[base + tid + 256] = aB1;
}

// ---------------- finalize: reduce partials, small GEMM to context ----------------
__global__ void k_final(const float* __restrict__ Wm, const float* __restrict__ bm,
                        float* __restrict__ out) {
    __shared__ float M[ENCx];
    __shared__ float sS[2];
    int b = blockIdx.x, tid = threadIdx.x;   // 256 threads
    if (tid == 0) {
        float S = 0.f, St = 0.f;
        for (int t = 0; t < NTILES; ++t) { S += g_pS[b * NTILES + t]; St += g_pSt[b * NTILES + t]; }
        sS[0] = S; sS[1] = St;
    }
    __syncthreads();
    float invS = 1.f / sS[0];
    for (int e = tid; e < ENCx; e += 256) {
        float a = 0.f, bb = 0.f;
        for (int t = 0; t < NTILES; ++t) {
            a  += g_pA[(b * NTILES + t) * ENCx + e];
            bb += g_pB[(b * NTILES + t) * ENCx + e];
        }
        M[e] = a + bb * invS;   // sum_t (state + s/S) * memory
    }
    __syncthreads();
    float cumsum = sS[1] + 1.f;              // sum_t cum = sum_t state + 1
    float acc = cumsum * bm[tid];
    #pragma unroll 4
    for (int e = 0; e < ENCx; ++e) acc = fmaf(M[e], Wm[e * Ux + tid], acc);
    out[b * Ux + tid] = acc;                 // context[b, 0, :]
}

// ---------------- launch ----------------
extern "C" void kernel_launch(void* const* d_in, const int* in_sizes, int n_in,
                              void* d_out, int out_size) {
    const float* query  = (const float*)d_in[0];
    const float* state  = (const float*)d_in[1];
    const float* memory = (const float*)d_in[2];
    const float* Wq     = (const float*)d_in[3];
    const float* bq     = (const float*)d_in[4];
    const float* Wm     = (const float*)d_in[5];
    const float* bm     = (const float*)d_in[6];
    const float* Wl     = (const float*)d_in[7];
    const float* bl     = (const float*)d_in[8];
    const float* conv_w = (const float*)d_in[9];
    const float* conv_b = (const float*)d_in[10];
    const float* We     = (const float*)d_in[11];
    const float* be     = (const float*)d_in[12];
    const float* v_a    = (const float*)d_in[13];
    float* out = (float*)d_out;

    k_wfold<<<ENCx + FILTx, Ux>>>(Wm, Wl, We);
    k_pqe<<<Bx, Ux>>>(query, Wq, bq, bl, bm, We, be);
    k_conv<<<Bx, 256>>>(state, conv_w, conv_b);
    k_main<<<Bx * NTILES, 256>>>(memory, state, v_a);
    k_final<<<Bx, Ux>>>(Wm, bm, out);
}

// round 4
// speedup vs baseline: 1.4077x; 1.4077x over previous
#include <cuda_runtime.h>
#include <cuda_bf16.h>
#include <math.h>
#include <stdint.h>

// Problem constants
#define Bx    64
#define Tt    2048
#define HIDx  1024
#define ENCx  512
#define Ux    256
#define FILTx 32
#define KWx   31
#define KTOT  (ENCx + FILTx)     // 544 : memory features + conv features folded
#define NCHUNK (KTOT / 16)       // 34 k-chunks of 16
#define BM    64
#define NTILES (Tt / BM)         // 32

// ---------------- scratch (device globals; no allocation allowed) ----------------
__device__ float          g_pqe[Bx * Ux];                    // fused per-batch bias
__device__ float          g_fT[(size_t)Bx * Tt * FILTx];     // conv output, t-major
__device__ __nv_bfloat16  g_Bhi[KTOT * Ux];                  // [Wm@We ; Wl@We] hi
__device__ __nv_bfloat16  g_Blo[KTOT * Ux];                  // lo residual
__device__ float          g_pA[Bx * NTILES * ENCx];          // sum_t state*mem per tile
__device__ float          g_pB[Bx * NTILES * ENCx];          // sum_t s*mem per tile
__device__ float          g_pS[Bx * NTILES];
__device__ float          g_pSt[Bx * NTILES];

// ---------------- PTX helpers ----------------
#define LDSM_X4(R, addr) \
    asm volatile("ldmatrix.sync.aligned.m8n8.x4.shared.b16 {%0,%1,%2,%3}, [%4];" \
        : "=r"((R)[0]), "=r"((R)[1]), "=r"((R)[2]), "=r"((R)[3]) : "r"(addr))

#define LDSM_X4T(R, addr) \
    asm volatile("ldmatrix.sync.aligned.m8n8.x4.trans.shared.b16 {%0,%1,%2,%3}, [%4];" \
        : "=r"((R)[0]), "=r"((R)[1]), "=r"((R)[2]), "=r"((R)[3]) : "r"(addr))

#define MMA16816(C, A, b0, b1) \
    asm volatile("mma.sync.aligned.m16n8k16.row.col.f32.bf16.bf16.f32 " \
        "{%0,%1,%2,%3},{%4,%5,%6,%7},{%8,%9},{%0,%1,%2,%3};" \
        : "+f"((C)[0]), "+f"((C)[1]), "+f"((C)[2]), "+f"((C)[3]) \
        : "r"((A)[0]), "r"((A)[1]), "r"((A)[2]), "r"((A)[3]), "r"(b0), "r"(b1))

static __device__ __forceinline__ uint32_t smem_u32(const void* p) {
    return (uint32_t)__cvta_generic_to_shared(p);
}

// ---------------- setup: weight folding + bf16 split ----------------
// row r<512: (Wm@We)[r,:], else (Wl@We)[r-512,:]; split into hi/lo bf16
__global__ void k_wfold(const float* __restrict__ Wm, const float* __restrict__ Wl,
                        const float* __restrict__ We) {
    int r = blockIdx.x;          // 0..543
    int u = threadIdx.x;         // 256
    const float* wrow = (r < ENCx) ? (Wm + r * Ux) : (Wl + (r - ENCx) * Ux);
    float a = 0.f;
    #pragma unroll 4
    for (int v = 0; v < Ux; ++v) a = fmaf(wrow[v], We[v * Ux + u], a);
    __nv_bfloat16 hi = __float2bfloat16(a);
    g_Bhi[r * Ux + u] = hi;
    g_Blo[r * Ux + u] = __float2bfloat16(a - __bfloat162float(hi));
}

// ---------------- setup: per-batch fused bias pqe ----------------
__global__ void k_pqe(const float* __restrict__ query, const float* __restrict__ Wq,
                      const float* __restrict__ bq, const float* __restrict__ bl,
                      const float* __restrict__ bm, const float* __restrict__ We,
                      const float* __restrict__ be) {
    __shared__ float tmp[Ux];
    int b = blockIdx.x, tid = threadIdx.x;
    const float* q = query + ((size_t)b * 2 + 1) * HIDx;
    float a = bq[tid] + bl[tid] + bm[tid];
    #pragma unroll 4
    for (int h = 0; h < HIDx; ++h) a = fmaf(q[h], Wq[h * Ux + tid], a);
    tmp[tid] = a;
    __syncthreads();
    float c = be[tid];
    #pragma unroll 4
    for (int v = 0; v < Ux; ++v) c = fmaf(tmp[v], We[v * Ux + tid], c);
    g_pqe[b * Ux + tid] = c;
}

// ---------------- setup: SAME conv, output t-major [b][t][32] ----------------
__global__ void k_conv(const float* __restrict__ state, const float* __restrict__ conv_w,
                       const float* __restrict__ conv_b) {
    __shared__ float xs[Tt + KWx - 1];
    __shared__ float ws[FILTx * KWx];
    int b = blockIdx.x, tid = threadIdx.x, nth = blockDim.x;
    for (int i = tid; i < Tt + KWx - 1; i += nth) {
        int t = i - (KWx - 1) / 2;
        xs[i] = (t >= 0 && t < Tt) ? state[b * Tt + t] : 0.f;
    }
    for (int i = tid; i < FILTx * KWx; i += nth) ws[i] = conv_w[i];
    __syncthreads();
    for (int f = 0; f < FILTx; ++f) {
        float cb = conv_b[f];
        const float* wf = &ws[f * KWx];
        for (int t = tid; t < Tt; t += nth) {
            float a = cb;
            #pragma unroll
            for (int k = 0; k < KWx; ++k) a = fmaf(wf[k], xs[t + k], a);
            g_fT[((size_t)b * Tt + t) * FILTx + f] = a;
        }
    }
}

// ---------------- main fused kernel: tensor-core GEMM + epilogue ----------------
// Block = (b, 64-row t-tile), 512 threads (16 warps: 4 m-warps x 4 n-warps).
// z[64,256] = [mem|f] @ [Bhi+Blo] via bf16-split mma.sync; then tanh/v_a/sigmoid,
// then state- and s-weighted memory sums (tile L1/L2-hot).
__global__ __launch_bounds__(512)
void k_main(const float* __restrict__ memory, const float* __restrict__ state,
            const float* __restrict__ v_a) {
    const int b    = blockIdx.x >> 5;
    const int tile = blockIdx.x & 31;
    const int t0   = tile * BM;

    __shared__ __nv_bfloat16 Ahi[64][24];    // [m][k], padded stride 24
    __shared__ __nv_bfloat16 Alo[64][24];
    __shared__ __nv_bfloat16 Bhi[16][264];   // [k][n], padded stride 264
    __shared__ __nv_bfloat16 Blo[16][264];
    __shared__ float pq_sm[Ux], va_sm[Ux];
    __shared__ float s_sm[BM], st_sm[BM];
    __shared__ float e_red[4][BM];

    const int tid  = threadIdx.x;
    const int lane = tid & 31;
    const int warp = tid >> 5;
    const int wm   = warp >> 2;              // 0..3 (16 rows each)
    const int wn   = warp & 3;               // 0..3 (64 cols each)

    if (tid < Ux) { pq_sm[tid] = g_pqe[b * Ux + tid]; va_sm[tid] = v_a[tid]; }
    if (tid < BM) st_sm[tid] = state[b * Tt + t0 + tid];

    const float* memb = memory + ((size_t)(b * Tt + t0)) * ENCx;

    // cooperative-load indices: A = 64x16 fp32, B = 16x256 bf16 (x2)
    const int ar = tid >> 3, ak = (tid & 7) * 2;   // one float2 per thread
    const int br = tid >> 5, bc = tid & 31;        // one uint4 per thread per matrix

    float acc[8][4];
    #pragma unroll
    for (int i = 0; i < 8; ++i) { acc[i][0] = 0.f; acc[i][1] = 0.f; acc[i][2] = 0.f; acc[i][3] = 0.f; }

    // prefetch chunk 0
    float2 aReg = *(const float2*)&memb[(size_t)ar * ENCx + ak];
    uint4 bhReg = ((const uint4*)g_Bhi)[br * 32 + bc];
    uint4 blReg = ((const uint4*)g_Blo)[br * 32 + bc];

    const uint32_t a_hi_addr = smem_u32(&Ahi[wm * 16 + (lane & 15)][(lane >> 4) * 8]);
    const uint32_t a_lo_addr = smem_u32(&Alo[wm * 16 + (lane & 15)][(lane >> 4) * 8]);

    for (int kt = 0; kt < NCHUNK; ++kt) {
        __syncthreads();
        // split A fp32 -> bf16 hi/lo, store to smem
        __nv_bfloat16 h0 = __float2bfloat16(aReg.x);
        Ahi[ar][ak]     = h0;
        Alo[ar][ak]     = __float2bfloat16(aReg.x - __bfloat162float(h0));
        __nv_bfloat16 h1 = __float2bfloat16(aReg.y);
        Ahi[ar][ak + 1] = h1;
        Alo[ar][ak + 1] = __float2bfloat16(aReg.y - __bfloat162float(h1));
        *(uint4*)&Bhi[br][bc * 8] = bhReg;
        *(uint4*)&Blo[br][bc * 8] = blReg;
        __syncthreads();

        // prefetch next chunk (overlaps with MMA below)
        int kn = kt + 1;
        if (kn < NCHUNK) {
            if (kn < ENCx / 16)
                aReg = *(const float2*)&memb[(size_t)ar * ENCx + kn * 16 + ak];
            else
                aReg = *(const float2*)&g_fT[((size_t)(b * Tt + t0 + ar)) * FILTx
                                             + (kn - ENCx / 16) * 16 + ak];
            bhReg = ((const uint4*)g_Bhi)[(kn * 16 + br) * 32 + bc];
            blReg = ((const uint4*)g_Blo)[(kn * 16 + br) * 32 + bc];
        }

        uint32_t ah[4], al[4];
        LDSM_X4(ah, a_hi_addr);
        LDSM_X4(al, a_lo_addr);

        #pragma unroll
        for (int p = 0; p < 4; ++p) {        // each x4.trans covers 2 n-tiles
            int n0 = wn * 64 + p * 16 + ((lane >> 4) << 3);
            uint32_t bh[4], bl4[4];
            uint32_t baddr_h = smem_u32(&Bhi[lane & 15][n0]);
            uint32_t baddr_l = smem_u32(&Blo[lane & 15][n0]);
            LDSM_X4T(bh, baddr_h);
            LDSM_X4T(bl4, baddr_l);
            // n-tile 2p
            MMA16816(acc[2 * p],     ah, bh[0],  bh[1]);
            MMA16816(acc[2 * p],     ah, bl4[0], bl4[1]);
            MMA16816(acc[2 * p],     al, bh[0],  bh[1]);
            // n-tile 2p+1
            MMA16816(acc[2 * p + 1], ah, bh[2],  bh[3]);
            MMA16816(acc[2 * p + 1], ah, bl4[2], bl4[3]);
            MMA16816(acc[2 * p + 1], al, bh[2],  bh[3]);
        }
    }

    // ---- epilogue: tanh, v_a dot, per-row energy reduce ----
    // C frag: c0 -> (row = wm*16 + lane/4, col = u0), c1 -> u0+1,
    //         c2 -> row+8 col u0, c3 -> row+8 col u0+1
    float e0 = 0.f, e1 = 0.f;
    #pragma unroll
    for (int nt = 0; nt < 8; ++nt) {
        int u0 = wn * 64 + nt * 8 + (lane & 3) * 2;
        float h;
        h = tanhf(acc[nt][0] + pq_sm[u0]);     e0 = fmaf(va_sm[u0],     h, e0);
        h = tanhf(acc[nt][1] + pq_sm[u0 + 1]); e0 = fmaf(va_sm[u0 + 1], h, e0);
        h = tanhf(acc[nt][2] + pq_sm[u0]);     e1 = fmaf(va_sm[u0],     h, e1);
        h = tanhf(acc[nt][3] + pq_sm[u0 + 1]); e1 = fmaf(va_sm[u0 + 1], h, e1);
    }
    e0 += __shfl_xor_sync(0xffffffffu, e0, 1);
    e0 += __shfl_xor_sync(0xffffffffu, e0, 2);
    e1 += __shfl_xor_sync(0xffffffffu, e1, 1);
    e1 += __shfl_xor_sync(0xffffffffu, e1, 2);
    if ((lane & 3) == 0) {
        int row = wm * 16 + (lane >> 2);
        e_red[wn][row]     = e0;
        e_red[wn][row + 8] = e1;
    }
    __syncthreads();
    if (tid < BM) {
        float E = e_red[0][tid] + e_red[1][tid] + e_red[2][tid] + e_red[3][tid];
        s_sm[tid] = 1.f / (1.f + expf(-E));
    }
    __syncthreads();

    if (tid < 32) {
        float S  = s_sm[tid]  + s_sm[tid + 32];
        float St = st_sm[tid] + st_sm[tid + 32];
        #pragma unroll
        for (int off = 16; off > 0; off >>= 1) {
            S  += __shfl_xor_sync(0xffffffffu, S, off);
            St += __shfl_xor_sync(0xffffffffu, St, off);
        }
        if (tid == 0) {
            g_pS[b * NTILES + tile]  = S;
            g_pSt[b * NTILES + tile] = St;
        }
    }

    // ---- weighted memory sums: one column per thread (ENC = 512 = blockDim) ----
    float aA = 0.f, aB = 0.f;
    const float* p = memb + tid;
    #pragma unroll 4
    for (int m = 0; m < BM; ++m) {
        float v = p[(size_t)m * ENCx];
        aA = fmaf(st_sm[m], v, aA);
        aB = fmaf(s_sm[m],  v, aB);
    }
    size_t base = (size_t)(b * NTILES + tile) * ENCx;
    g_pA[base + tid] = aA;
    g_pB[base + tid] = aB;
}

// ---------------- finalize: reduce partials, small GEMM to context ----------------
__global__ void k_final(const float* __restrict__ Wm, const float* __restrict__ bm,
                        float* __restrict__ out) {
    __shared__ float M[ENCx];
    __shared__ float sS[2];
    int b = blockIdx.x, tid = threadIdx.x;   // 256 threads
    if (tid == 0) {
        float S = 0.f, St = 0.f;
        for (int t = 0; t < NTILES; ++t) { S += g_pS[b * NTILES + t]; St += g_pSt[b * NTILES + t]; }
        sS[0] = S; sS[1] = St;
    }
    __syncthreads();
    float invS = 1.f / sS[0];
    for (int e = tid; e < ENCx; e += 256) {
        float a = 0.f, bb = 0.f;
        for (int t = 0; t < NTILES; ++t) {
            a  += g_pA[(b * NTILES + t) * ENCx + e];
            bb += g_pB[(b * NTILES + t) * ENCx + e];
        }
        M[e] = a + bb * invS;
    }
    __syncthreads();
    float cumsum = sS[1] + 1.f;
    float acc = cumsum * bm[tid];
    #pragma unroll 4
    for (int e = 0; e < ENCx; ++e) acc = fmaf(M[e], Wm[e * Ux + tid], acc);
    out[b * Ux + tid] = acc;
}

// ---------------- launch ----------------
extern "C" void kernel_launch(void* const* d_in, const int* in_sizes, int n_in,
                              void* d_out, int out_size) {
    const float* query  = (const float*)d_in[0];
    const float* state  = (const float*)d_in[1];
    const float* memory = (const float*)d_in[2];
    const float* Wq     = (const float*)d_in[3];
    const float* bq     = (const float*)d_in[4];
    const float* Wm     = (const float*)d_in[5];
    const float* bm     = (const float*)d_in[6];
    const float* Wl     = (const float*)d_in[7];
    const float* bl     = (const float*)d_in[8];
    const float* conv_w = (const float*)d_in[9];
    const float* conv_b = (const float*)d_in[10];
    const float* We     = (const float*)d_in[11];
    const float* be     = (const float*)d_in[12];
    const float* v_a    = (const float*)d_in[13];
    float* out = (float*)d_out;

    k_wfold<<<KTOT, Ux>>>(Wm, Wl, We);
    k_pqe<<<Bx, Ux>>>(query, Wq, bq, bl, bm, We, be);
    k_conv<<<Bx, 256>>>(state, conv_w, conv_b);
    k_main<<<Bx * NTILES, 512>>>(memory, state, v_a);
    k_final<<<Bx, Ux>>>(Wm, bm, out);
}

// round 5
// speedup vs baseline: 1.8811x; 1.3363x over previous
#include <cuda_runtime.h>
#include <cuda_bf16.h>
#include <math.h>
#include <stdint.h>

// Problem constants
#define Bx    64
#define Tt    2048
#define HIDx  1024
#define ENCx  512
#define Ux    256
#define FILTx 32
#define KWx   31
#define KTOT  (ENCx + FILTx)     // 544
#define NCHUNK (KTOT / 16)       // 34
#define BM    64
#define NTILES (Tt / BM)         // 32

// ---------------- scratch ----------------
__device__ float          g_pqe[Bx * Ux];
__device__ float          g_fT[(size_t)Bx * Tt * FILTx];     // conv output, t-major
__device__ __nv_bfloat16  g_Bw[KTOT * Ux];                   // [Wm@We ; Wl@We] bf16
__device__ float          g_pA[Bx * NTILES * ENCx];
__device__ float          g_pB[Bx * NTILES * ENCx];
__device__ float          g_pS[Bx * NTILES];
__device__ float          g_pSt[Bx * NTILES];

// ---------------- PTX helpers ----------------
#define LDSM_X4(R, addr) \
    asm volatile("ldmatrix.sync.aligned.m8n8.x4.shared.b16 {%0,%1,%2,%3}, [%4];" \
        : "=r"((R)[0]), "=r"((R)[1]), "=r"((R)[2]), "=r"((R)[3]) : "r"(addr))

#define LDSM_X4T(R, addr) \
    asm volatile("ldmatrix.sync.aligned.m8n8.x4.trans.shared.b16 {%0,%1,%2,%3}, [%4];" \
        : "=r"((R)[0]), "=r"((R)[1]), "=r"((R)[2]), "=r"((R)[3]) : "r"(addr))

#define MMA16816(C, A, b0, b1) \
    asm volatile("mma.sync.aligned.m16n8k16.row.col.f32.bf16.bf16.f32 " \
        "{%0,%1,%2,%3},{%4,%5,%6,%7},{%8,%9},{%0,%1,%2,%3};" \
        : "+f"((C)[0]), "+f"((C)[1]), "+f"((C)[2]), "+f"((C)[3]) \
        : "r"((A)[0]), "r"((A)[1]), "r"((A)[2]), "r"((A)[3]), "r"(b0), "r"(b1))

static __device__ __forceinline__ uint32_t smem_u32(const void* p) {
    return (uint32_t)__cvta_generic_to_shared(p);
}
static __device__ __forceinline__ float tanh_fast(float x) {
    float y; asm("tanh.approx.f32 %0, %1;" : "=f"(y) : "f"(x)); return y;
}

// ---------------- fused setup kernel (wfold | pqe | conv) ----------------
__global__ void k_setup(const float* __restrict__ Wm, const float* __restrict__ Wl,
                        const float* __restrict__ We, const float* __restrict__ query,
                        const float* __restrict__ Wq, const float* __restrict__ bq,
                        const float* __restrict__ bl, const float* __restrict__ bm,
                        const float* __restrict__ be, const float* __restrict__ state,
                        const float* __restrict__ conv_w, const float* __restrict__ conv_b) {
    __shared__ float sh[Tt + KWx - 1 + FILTx * KWx];   // reused across sections
    const int bid = blockIdx.x, tid = threadIdx.x;     // 256 threads

    if (bid < KTOT) {
        // ---- weight folding: g_Bw[r,:] = (Wm|Wl)[r,:] @ We, bf16 ----
        const float* wrow = (bid < ENCx) ? (Wm + bid * Ux) : (Wl + (bid - ENCx) * Ux);
        float a = 0.f;
        #pragma unroll 4
        for (int v = 0; v < Ux; ++v) a = fmaf(wrow[v], We[v * Ux + tid], a);
        g_Bw[bid * Ux + tid] = __float2bfloat16(a);
    } else if (bid < KTOT + Bx) {
        // ---- pqe[b,:] = (q@Wq + bq + bl + bm) @ We + be ----
        const int b = bid - KTOT;
        const float* q = query + ((size_t)b * 2 + 1) * HIDx;
        float a = bq[tid] + bl[tid] + bm[tid];
        #pragma unroll 4
        for (int h = 0; h < HIDx; ++h) a = fmaf(q[h], Wq[h * Ux + tid], a);
        sh[tid] = a;
        __syncthreads();
        float c = be[tid];
        #pragma unroll 4
        for (int v = 0; v < Ux; ++v) c = fmaf(sh[v], We[v * Ux + tid], c);
        g_pqe[b * Ux + tid] = c;
    } else {
        // ---- SAME conv over state, output t-major [b][t][32] ----
        const int b = bid - KTOT - Bx;
        float* xs = sh;
        float* ws = sh + (Tt + KWx - 1);
        for (int i = tid; i < Tt + KWx - 1; i += 256) {
            int t = i - (KWx - 1) / 2;
            xs[i] = (t >= 0 && t < Tt) ? state[b * Tt + t] : 0.f;
        }
        for (int i = tid; i < FILTx * KWx; i += 256) ws[i] = conv_w[i];
        __syncthreads();
        for (int f = 0; f < FILTx; ++f) {
            float cb = conv_b[f];
            const float* wf = &ws[f * KWx];
            for (int t = tid; t < Tt; t += 256) {
                float a = cb;
                #pragma unroll
                for (int k = 0; k < KWx; ++k) a = fmaf(wf[k], xs[t + k], a);
                g_fT[((size_t)b * Tt + t) * FILTx + f] = a;
            }
        }
    }
}

// ---------------- main fused kernel ----------------
// Block = (b, 64-row t-tile), 512 threads (16 warps: 4 m x 4 n).
// z[64,256] = bf16([mem|f]) @ g_Bw via mma.sync; tanh/v_a/sigmoid epilogue;
// then state- and s-weighted memory column sums.
__global__ __launch_bounds__(512, 2)
void k_main(const float* __restrict__ memory, const float* __restrict__ state,
            const float* __restrict__ v_a) {
    const int b    = blockIdx.x >> 5;
    const int tile = blockIdx.x & 31;
    const int t0   = tile * BM;

    __shared__ __nv_bfloat16 Asm[2][64][24];    // [buf][m][k], stride 24
    __shared__ __nv_bfloat16 Bsm[2][16][264];   // [buf][k][n], stride 264
    __shared__ float pq_sm[Ux], va_sm[Ux];
    __shared__ float s_sm[BM], st_sm[BM];
    __shared__ float e_red[4][BM];

    const int tid  = threadIdx.x;
    const int lane = tid & 31;
    const int warp = tid >> 5;
    const int wm   = warp >> 2;               // 0..3
    const int wn   = warp & 3;                // 0..3

    if (tid < Ux) { pq_sm[tid] = g_pqe[b * Ux + tid]; va_sm[tid] = v_a[tid]; }
    if (tid < BM) st_sm[tid] = state[b * Tt + t0 + tid];

    const float* memb = memory + ((size_t)(b * Tt + t0)) * ENCx;

    const int ar = tid >> 3, ak = (tid & 7) * 2;   // A: float2 per thread
    const int br = tid >> 5, bc = tid & 31;        // B: uint4 per thread

    float acc[8][4];
    #pragma unroll
    for (int i = 0; i < 8; ++i) { acc[i][0]=0.f; acc[i][1]=0.f; acc[i][2]=0.f; acc[i][3]=0.f; }

    // prefetch chunk 0 into registers
    float2 aReg = *(const float2*)&memb[(size_t)ar * ENCx + ak];
    uint4  bReg = ((const uint4*)g_Bw)[br * 32 + bc];

    #pragma unroll 1
    for (int kt = 0; kt < NCHUNK; ++kt) {
        const int buf = kt & 1;
        // store chunk kt (A converted to bf16x2 packed, B raw)
        *(__nv_bfloat162*)&Asm[buf][ar][ak] =
            __float22bfloat162_rn(make_float2(aReg.x, aReg.y));
        *(uint4*)&Bsm[buf][br][bc * 8] = bReg;
        __syncthreads();

        // prefetch chunk kt+1 (overlaps with MMA)
        const int kn = kt + 1;
        if (kn < NCHUNK) {
            if (kn < ENCx / 16)
                aReg = *(const float2*)&memb[(size_t)ar * ENCx + kn * 16 + ak];
            else
                aReg = *(const float2*)&g_fT[((size_t)(b * Tt + t0 + ar)) * FILTx
                                             + (kn - ENCx / 16) * 16 + ak];
            bReg = ((const uint4*)g_Bw)[(kn * 16 + br) * 32 + bc];
        }

        uint32_t af[4];
        LDSM_X4(af, smem_u32(&Asm[buf][wm * 16 + (lane & 15)][(lane >> 4) * 8]));
        #pragma unroll
        for (int p = 0; p < 4; ++p) {
            int n0 = wn * 64 + p * 16 + ((lane >> 4) << 3);
            uint32_t bf[4];
            LDSM_X4T(bf, smem_u32(&Bsm[buf][lane & 15][n0]));
            MMA16816(acc[2 * p],     af, bf[0], bf[1]);
            MMA16816(acc[2 * p + 1], af, bf[2], bf[3]);
        }
        // single barrier per chunk: next iter's STS targets the other buffer;
        // bar.sync here orders this iter's LDSM before its buffer is refilled.
        __syncthreads();
    }

    // ---- epilogue: tanh (MUFU), v_a dot, per-row energy reduce ----
    float e0 = 0.f, e1 = 0.f;
    #pragma unroll
    for (int nt = 0; nt < 8; ++nt) {
        int u0 = wn * 64 + nt * 8 + (lane & 3) * 2;
        e0 = fmaf(va_sm[u0],     tanh_fast(acc[nt][0] + pq_sm[u0]),     e0);
        e0 = fmaf(va_sm[u0 + 1], tanh_fast(acc[nt][1] + pq_sm[u0 + 1]), e0);
        e1 = fmaf(va_sm[u0],     tanh_fast(acc[nt][2] + pq_sm[u0]),     e1);
        e1 = fmaf(va_sm[u0 + 1], tanh_fast(acc[nt][3] + pq_sm[u0 + 1]), e1);
    }
    e0 += __shfl_xor_sync(0xffffffffu, e0, 1);
    e0 += __shfl_xor_sync(0xffffffffu, e0, 2);
    e1 += __shfl_xor_sync(0xffffffffu, e1, 1);
    e1 += __shfl_xor_sync(0xffffffffu, e1, 2);
    if ((lane & 3) == 0) {
        int row = wm * 16 + (lane >> 2);
        e_red[wn][row]     = e0;
        e_red[wn][row + 8] = e1;
    }
    __syncthreads();
    if (tid < BM) {
        float E = e_red[0][tid] + e_red[1][tid] + e_red[2][tid] + e_red[3][tid];
        s_sm[tid] = 1.f / (1.f + __expf(-E));
    }
    __syncthreads();

    if (tid < 32) {
        float S  = s_sm[tid]  + s_sm[tid + 32];
        float St = st_sm[tid] + st_sm[tid + 32];
        #pragma unroll
        for (int off = 16; off > 0; off >>= 1) {
            S  += __shfl_xor_sync(0xffffffffu, S, off);
            St += __shfl_xor_sync(0xffffffffu, St, off);
        }
        if (tid == 0) {
            g_pS[b * NTILES + tile]  = S;
            g_pSt[b * NTILES + tile] = St;
        }
    }

    // ---- weighted memory column sums (ENC = 512 = blockDim) ----
    float aA = 0.f, aB = 0.f;
    const float* p = memb + tid;
    #pragma unroll 4
    for (int m = 0; m < BM; ++m) {
        float v = p[(size_t)m * ENCx];
        aA = fmaf(st_sm[m], v, aA);
        aB = fmaf(s_sm[m],  v, aB);
    }
    size_t base = (size_t)(b * NTILES + tile) * ENCx;
    g_pA[base + tid] = aA;
    g_pB[base + tid] = aB;
}

// ---------------- finalize ----------------
__global__ void k_final(const float* __restrict__ Wm, const float* __restrict__ bm,
                        float* __restrict__ out) {
    __shared__ float M[ENCx];
    __shared__ float sS[2];
    int b = blockIdx.x, tid = threadIdx.x;   // 256 threads
    if (tid == 0) {
        float S = 0.f, St = 0.f;
        for (int t = 0; t < NTILES; ++t) { S += g_pS[b * NTILES + t]; St += g_pSt[b * NTILES + t]; }
        sS[0] = S; sS[1] = St;
    }
    __syncthreads();
    float invS = 1.f / sS[0];
    for (int e = tid; e < ENCx; e += 256) {
        float a = 0.f, bb = 0.f;
        for (int t = 0; t < NTILES; ++t) {
            a  += g_pA[(b * NTILES + t) * ENCx + e];
            bb += g_pB[(b * NTILES + t) * ENCx + e];
        }
        M[e] = a + bb * invS;
    }
    __syncthreads();
    float cumsum = sS[1] + 1.f;
    float acc = cumsum * bm[tid];
    #pragma unroll 4
    for (int e = 0; e < ENCx; ++e) acc = fmaf(M[e], Wm[e * Ux + tid], acc);
    out[b * Ux + tid] = acc;
}

// ---------------- launch ----------------
extern "C" void kernel_launch(void* const* d_in, const int* in_sizes, int n_in,
                              void* d_out, int out_size) {
    const float* query  = (const float*)d_in[0];
    const float* state  = (const float*)d_in[1];
    const float* memory = (const float*)d_in[2];
    const float* Wq     = (const float*)d_in[3];
    const float* bq     = (const float*)d_in[4];
    const float* Wm     = (const float*)d_in[5];
    const float* bm     = (const float*)d_in[6];
    const float* Wl     = (const float*)d_in[7];
    const float* bl     = (const float*)d_in[8];
    const float* conv_w = (const float*)d_in[9];
    const float* conv_b = (const float*)d_in[10];
    const float* We     = (const float*)d_in[11];
    const float* be     = (const float*)d_in[12];
    const float* v_a    = (const float*)d_in[13];
    float* out = (float*)d_out;

    k_setup<<<KTOT + 2 * Bx, 256>>>(Wm, Wl, We, query, Wq, bq, bl, bm, be,
                                    state, conv_w, conv_b);
    k_main<<<Bx * NTILES, 512>>>(memory, state, v_a);
    k_final<<<Bx, Ux>>>(Wm, bm, out);
}

// round 6
// speedup vs baseline: 2.8848x; 1.5336x over previous
#include <cuda_runtime.h>
#include <cuda_bf16.h>
#include <math.h>
#include <stdint.h>

// Problem constants
#define Bx    64
#define Tt    2048
#define HIDx  1024
#define ENCx  512
#define Ux    256
#define FILTx 32
#define KWx   31
#define KTOT  (ENCx + FILTx)     // 544: 512 memory chunks + 2 conv-window chunks
#define NCHUNK (KTOT / 16)       // 34
#define BM    64
#define NTILES (Tt / BM)         // 32

// ---------------- scratch ----------------
__device__ float          g_pqe[Bx * Ux];
__device__ float          g_biasc[Ux];                 // conv_b @ Wle
__device__ __nv_bfloat16  g_Bw[KTOT * Ux];             // [Wm@We(512) ; G(31) ; 0(1)]
__device__ float          g_pA[Bx * NTILES * ENCx];
__device__ float          g_pB[Bx * NTILES * ENCx];
__device__ float          g_pS[Bx * NTILES];
__device__ float          g_pSt[Bx * NTILES];

// ---------------- PTX helpers ----------------
#define LDSM_X4(R, addr) \
    asm volatile("ldmatrix.sync.aligned.m8n8.x4.shared.b16 {%0,%1,%2,%3}, [%4];" \
        : "=r"((R)[0]), "=r"((R)[1]), "=r"((R)[2]), "=r"((R)[3]) : "r"(addr))

#define LDSM_X4T(R, addr) \
    asm volatile("ldmatrix.sync.aligned.m8n8.x4.trans.shared.b16 {%0,%1,%2,%3}, [%4];" \
        : "=r"((R)[0]), "=r"((R)[1]), "=r"((R)[2]), "=r"((R)[3]) : "r"(addr))

#define MMA16816(C, A, b0, b1) \
    asm volatile("mma.sync.aligned.m16n8k16.row.col.f32.bf16.bf16.f32 " \
        "{%0,%1,%2,%3},{%4,%5,%6,%7},{%8,%9},{%0,%1,%2,%3};" \
        : "+f"((C)[0]), "+f"((C)[1]), "+f"((C)[2]), "+f"((C)[3]) \
        : "r"((A)[0]), "r"((A)[1]), "r"((A)[2]), "r"((A)[3]), "r"(b0), "r"(b1))

static __device__ __forceinline__ uint32_t smem_u32(const void* p) {
    return (uint32_t)__cvta_generic_to_shared(p);
}
static __device__ __forceinline__ float tanh_fast(float x) {
    float y; asm("tanh.approx.f32 %0, %1;" : "=f"(y) : "f"(x)); return y;
}

// ---------------- setup kernel: 41 blocks x 256 threads, high-ILP tiles ----------------
// bid 0..31  : wfold rows bid*16..+16 of Wm@We -> g_Bw (16 accumulators/thread)
// bid 32     : Wle = Wl@We (32 acc), then G = conv_w^T@Wle, biasc = conv_b@Wle
// bid 33..40 : pqe for 8 batches each (8 accumulators/thread, 2 stages)
__global__ __launch_bounds__(256)
void k_setup(const float* __restrict__ Wm, const float* __restrict__ Wl,
             const float* __restrict__ We, const float* __restrict__ query,
             const float* __restrict__ Wq, const float* __restrict__ bq,
             const float* __restrict__ bl, const float* __restrict__ bm,
             const float* __restrict__ be, const float* __restrict__ conv_w,
             const float* __restrict__ conv_b) {
    __shared__ float sh[10240];          // 40KB, sectioned per branch
    const int bid = blockIdx.x, tid = threadIdx.x;

    if (bid < 32) {
        // ---- Wm@We rows [r0, r0+16) ----
        const int r0 = bid * 16;
        float* w_sm = sh;                // [16][256]
        #pragma unroll
        for (int r = 0; r < 16; ++r) w_sm[r * 256 + tid] = Wm[(size_t)(r0 + r) * Ux + tid];
        __syncthreads();
        float acc[16];
        #pragma unroll
        for (int r = 0; r < 16; ++r) acc[r] = 0.f;
        #pragma unroll 4
        for (int v = 0; v < Ux; ++v) {
            float we = We[v * Ux + tid];
            #pragma unroll
            for (int r = 0; r < 16; ++r) acc[r] = fmaf(w_sm[r * 256 + v], we, acc[r]);
        }
        #pragma unroll
        for (int r = 0; r < 16; ++r)
            g_Bw[(size_t)(r0 + r) * Ux + tid] = __float2bfloat16(acc[r]);
    } else if (bid == 32) {
        // ---- Wle = Wl@We, then G and biasc ----
        float* wl_sm = sh;               // [32][256]
        for (int i = tid; i < FILTx * Ux; i += 256) wl_sm[i] = Wl[i];
        __syncthreads();
        float acc[32];
        #pragma unroll
        for (int f = 0; f < 32; ++f) acc[f] = 0.f;
        #pragma unroll 4
        for (int v = 0; v < Ux; ++v) {
            float we = We[v * Ux + tid];
            #pragma unroll
            for (int f = 0; f < 32; ++f) acc[f] = fmaf(wl_sm[f * 256 + v], we, acc[f]);
        }
        __syncthreads();                 // all wl_sm reads done before overwrite
        #pragma unroll
        for (int f = 0; f < 32; ++f) wl_sm[f * 256 + tid] = acc[f];   // now Wle
        __syncthreads();
        #pragma unroll 1
        for (int k = 0; k < KWx; ++k) {
            float g = 0.f;
            #pragma unroll
            for (int f = 0; f < 32; ++f) g = fmaf(conv_w[f * KWx + k], wl_sm[f * 256 + tid], g);
            g_Bw[(size_t)(ENCx + k) * Ux + tid] = __float2bfloat16(g);
        }
        g_Bw[(size_t)(KTOT - 1) * Ux + tid] = __float2bfloat16(0.f);  // pad row
        float bc = 0.f;
        #pragma unroll
        for (int f = 0; f < 32; ++f) bc = fmaf(conv_b[f], wl_sm[f * 256 + tid], bc);
        g_biasc[tid] = bc;
    } else {
        // ---- pqe for batches [b0, b0+8) ----
        const int b0 = (bid - 33) * 8;
        float* q_sm  = sh;               // [8][1024]
        float* t_sm  = sh + 8 * 1024;    // [8][256]
        #pragma unroll
        for (int j = 0; j < 32; ++j) {
            int idx = j * 256 + tid;     // 8192 loads
            int bb = idx >> 10, h = idx & 1023;
            q_sm[idx] = query[((size_t)(b0 + bb) * 2 + 1) * HIDx + h];
        }
        __syncthreads();
        float a[8];
        #pragma unroll
        for (int j = 0; j < 8; ++j) a[j] = 0.f;
        #pragma unroll 4
        for (int h = 0; h < HIDx; ++h) {
            float wq = Wq[(size_t)h * Ux + tid];
            #pragma unroll
            for (int j = 0; j < 8; ++j) a[j] = fmaf(q_sm[j * 1024 + h], wq, a[j]);
        }
        float base = bq[tid] + bl[tid] + bm[tid];
        #pragma unroll
        for (int j = 0; j < 8; ++j) t_sm[j * 256 + tid] = a[j] + base;
        __syncthreads();
        float c[8];
        #pragma unroll
        for (int j = 0; j < 8; ++j) c[j] = be[tid];
        #pragma unroll 4
        for (int v = 0; v < Ux; ++v) {
            float we = We[v * Ux + tid];
            #pragma unroll
            for (int j = 0; j < 8; ++j) c[j] = fmaf(t_sm[j * 256 + v], we, c[j]);
        }
        #pragma unroll
        for (int j = 0; j < 8; ++j) g_pqe[(size_t)(b0 + j) * Ux + tid] = c[j];
    }
}

// ---------------- main fused kernel ----------------
// Block = (b, 64-row t-tile), 256 threads, 8 warps (2m x 4n), warp = 32 rows x 64 cols.
// K = 34 chunks: 32 from memory, 2 from shifted state windows (conv fold).
__global__ __launch_bounds__(256, 2)
void k_main(const float* __restrict__ memory, const float* __restrict__ state,
            const float* __restrict__ v_a) {
    const int b    = blockIdx.x >> 5;
    const int tile = blockIdx.x & 31;
    const int t0   = tile * BM;

    __shared__ __nv_bfloat16 Asm[2][64][24];    // [buf][m][k], 48B row stride
    __shared__ __nv_bfloat16 Bsm[2][16][264];   // [buf][k][n], 528B row stride
    __shared__ float pq_sm[Ux], va_sm[Ux];
    __shared__ float s_sm[BM], st_sm[BM];
    __shared__ float se[96];                    // state window [t0-15, t0+80)
    __shared__ float e_red[4][BM];

    const int tid  = threadIdx.x;
    const int lane = tid & 31;
    const int warp = tid >> 5;
    const int wm   = warp >> 2;                 // 0..1 (32 rows each)
    const int wn   = warp & 3;                  // 0..3 (64 cols each)

    pq_sm[tid] = g_pqe[b * Ux + tid] + g_biasc[tid];
    va_sm[tid] = v_a[tid];
    if (tid < BM) st_sm[tid] = state[b * Tt + t0 + tid];
    if (tid < 95) {
        int t = t0 + tid - 15;
        se[tid] = (t >= 0 && t < Tt) ? state[b * Tt + t] : 0.f;
    }

    const float* memb = memory + ((size_t)(b * Tt + t0)) * ENCx;

    const int ar = tid >> 2, ak = (tid & 3) * 4;    // A: float4 per thread
    const int br = tid >> 5, bc2 = tid & 31;        // B: 2 x uint4 per thread

    float acc[16][4];
    #pragma unroll
    for (int i = 0; i < 16; ++i) { acc[i][0]=0.f; acc[i][1]=0.f; acc[i][2]=0.f; acc[i][3]=0.f; }

    // prefetch chunk 0
    float4 aReg = *(const float4*)&memb[(size_t)ar * ENCx + ak];
    uint4  bReg0 = ((const uint4*)g_Bw)[(size_t)br * 32 + bc2];
    uint4  bReg1 = ((const uint4*)g_Bw)[(size_t)(br + 8) * 32 + bc2];

    const uint32_t a_addr0 = smem_u32(&Asm[0][wm * 32 + (lane & 15)][(lane >> 4) * 8]);
    const int      a_buf_stride = (int)(sizeof(__nv_bfloat16) * 64 * 24);

    #pragma unroll 1
    for (int kt = 0; kt < NCHUNK; ++kt) {
        const int buf = kt & 1;
        // store chunk kt
        __nv_bfloat162 p0 = __float22bfloat162_rn(make_float2(aReg.x, aReg.y));
        __nv_bfloat162 p1 = __float22bfloat162_rn(make_float2(aReg.z, aReg.w));
        *(__nv_bfloat162*)&Asm[buf][ar][ak]     = p0;
        *(__nv_bfloat162*)&Asm[buf][ar][ak + 2] = p1;
        *(uint4*)&Bsm[buf][br][bc2 * 8]     = bReg0;
        *(uint4*)&Bsm[buf][br + 8][bc2 * 8] = bReg1;
        __syncthreads();   // single barrier per chunk (see buffer-hazard argument)

        // prefetch chunk kt+1
        const int kn = kt + 1;
        if (kn < ENCx / 16) {
            aReg = *(const float4*)&memb[(size_t)ar * ENCx + kn * 16 + ak];
        } else if (kn < NCHUNK) {
            int kk0 = (kn - ENCx / 16) * 16 + ak;
            aReg.x = se[ar + kk0];     aReg.y = se[ar + kk0 + 1];
            aReg.z = se[ar + kk0 + 2]; aReg.w = se[ar + kk0 + 3];
        }
        if (kn < NCHUNK) {
            bReg0 = ((const uint4*)g_Bw)[(size_t)(kn * 16 + br) * 32 + bc2];
            bReg1 = ((const uint4*)g_Bw)[(size_t)(kn * 16 + br + 8) * 32 + bc2];
        }

        uint32_t a0[4], a1[4];
        LDSM_X4(a0, a_addr0 + buf * a_buf_stride);
        LDSM_X4(a1, a_addr0 + buf * a_buf_stride + 16 * 48);   // +16 rows
        #pragma unroll
        for (int p = 0; p < 4; ++p) {
            int n0 = wn * 64 + p * 16 + ((lane >> 4) << 3);
            uint32_t bf[4];
            LDSM_X4T(bf, smem_u32(&Bsm[buf][lane & 15][n0]));
            MMA16816(acc[2 * p],         a0, bf[0], bf[1]);
            MMA16816(acc[2 * p + 1],     a0, bf[2], bf[3]);
            MMA16816(acc[8 + 2 * p],     a1, bf[0], bf[1]);
            MMA16816(acc[8 + 2 * p + 1], a1, bf[2], bf[3]);
        }
    }

    // ---- epilogue: tanh (MUFU), v_a dot, per-row energy reduce ----
    #pragma unroll
    for (int mt = 0; mt < 2; ++mt) {
        float e0 = 0.f, e1 = 0.f;
        #pragma unroll
        for (int nt = 0; nt < 8; ++nt) {
            const float* c = acc[mt * 8 + nt];
            int u0 = wn * 64 + nt * 8 + (lane & 3) * 2;
            e0 = fmaf(va_sm[u0],     tanh_fast(c[0] + pq_sm[u0]),     e0);
            e0 = fmaf(va_sm[u0 + 1], tanh_fast(c[1] + pq_sm[u0 + 1]), e0);
            e1 = fmaf(va_sm[u0],     tanh_fast(c[2] + pq_sm[u0]),     e1);
            e1 = fmaf(va_sm[u0 + 1], tanh_fast(c[3] + pq_sm[u0 + 1]), e1);
        }
        e0 += __shfl_xor_sync(0xffffffffu, e0, 1);
        e0 += __shfl_xor_sync(0xffffffffu, e0, 2);
        e1 += __shfl_xor_sync(0xffffffffu, e1, 1);
        e1 += __shfl_xor_sync(0xffffffffu, e1, 2);
        if ((lane & 3) == 0) {
            int row = wm * 32 + mt * 16 + (lane >> 2);
            e_red[wn][row]     = e0;
            e_red[wn][row + 8] = e1;
        }
    }
    __syncthreads();
    if (tid < BM) {
        float E = e_red[0][tid] + e_red[1][tid] + e_red[2][tid] + e_red[3][tid];
        s_sm[tid] = 1.f / (1.f + __expf(-E));
    }
    __syncthreads();

    if (tid < 32) {
        float S  = s_sm[tid]  + s_sm[tid + 32];
        float St = st_sm[tid] + st_sm[tid + 32];
        #pragma unroll
        for (int off = 16; off > 0; off >>= 1) {
            S  += __shfl_xor_sync(0xffffffffu, S, off);
            St += __shfl_xor_sync(0xffffffffu, St, off);
        }
        if (tid == 0) {
            g_pS[b * NTILES + tile]  = S;
            g_pSt[b * NTILES + tile] = St;
        }
    }

    // ---- weighted memory column sums: 2 columns per thread ----
    float aA0 = 0.f, aB0 = 0.f, aA1 = 0.f, aB1 = 0.f;
    const float* p0 = memb + tid;
    const float* p1 = memb + tid + 256;
    #pragma unroll 4
    for (int m = 0; m < BM; ++m) {
        float v0 = p0[(size_t)m * ENCx];
        float v1 = p1[(size_t)m * ENCx];
        float sw = s_sm[m], stw = st_sm[m];
        aA0 = fmaf(stw, v0, aA0);  aB0 = fmaf(sw, v0, aB0);
        aA1 = fmaf(stw, v1, aA1);  aB1 = fmaf(sw, v1, aB1);
    }
    size_t base = (size_t)(b * NTILES + tile) * ENCx;
    g_pA[base + tid]       = aA0;
    g_pA[base + tid + 256] = aA1;
    g_pB[base + tid]       = aB0;
    g_pB[base + tid + 256] = aB1;
}

// ---------------- finalize ----------------
__global__ void k_final(const float* __restrict__ Wm, const float* __restrict__ bm,
                        float* __restrict__ out) {
    __shared__ float M[ENCx];
    __shared__ float sS[2];
    int b = blockIdx.x, tid = threadIdx.x;   // 256 threads
    if (tid == 0) {
        float S = 0.f, St = 0.f;
        for (int t = 0; t < NTILES; ++t) { S += g_pS[b * NTILES + t]; St += g_pSt[b * NTILES + t]; }
        sS[0] = S; sS[1] = St;
    }
    __syncthreads();
    float invS = 1.f / sS[0];
    for (int e = tid; e < ENCx; e += 256) {
        float a = 0.f, bb = 0.f;
        for (int t = 0; t < NTILES; ++t) {
            a  += g_pA[(b * NTILES + t) * ENCx + e];
            bb += g_pB[(b * NTILES + t) * ENCx + e];
        }
        M[e] = a + bb * invS;
    }
    __syncthreads();
    float cumsum = sS[1] + 1.f;
    float acc = cumsum * bm[tid];
    #pragma unroll 4
    for (int e = 0; e < ENCx; ++e) acc = fmaf(M[e], Wm[e * Ux + tid], acc);
    out[b * Ux + tid] = acc;
}

// ---------------- launch ----------------
extern "C" void kernel_launch(void* const* d_in, const int* in_sizes, int n_in,
                              void* d_out, int out_size) {
    const float* query  = (const float*)d_in[0];
    const float* state  = (const float*)d_in[1];
    const float* memory = (const float*)d_in[2];
    const float* Wq     = (const float*)d_in[3];
    const float* bq     = (const float*)d_in[4];
    const float* Wm     = (const float*)d_in[5];
    const float* bm     = (const float*)d_in[6];
    const float* Wl     = (const float*)d_in[7];
    const float* bl     = (const float*)d_in[8];
    const float* conv_w = (const float*)d_in[9];
    const float* conv_b = (const float*)d_in[10];
    const float* We     = (const float*)d_in[11];
    const float* be     = (const float*)d_in[12];
    const float* v_a    = (const float*)d_in[13];
    float* out = (float*)d_out;

    k_setup<<<41, 256>>>(Wm, Wl, We, query, Wq, bq, bl, bm, be, conv_w, conv_b);
    k_main<<<Bx * NTILES, 256>>>(memory, state, v_a);
    k_final<<<Bx, Ux>>>(Wm, bm, out);
}

// round 7
// speedup vs baseline: 3.7413x; 1.2969x over previous
#include <cuda_runtime.h>
#include <cuda_bf16.h>
#include <math.h>
#include <stdint.h>

// Problem constants
#define Bx    64
#define Tt    2048
#define HIDx  1024
#define ENCx  512
#define Ux    256
#define FILTx 32
#define KWx   31
#define KTOT  (ENCx + FILTx)     // 544: 512 memory-k + 31 conv-k + 1 pad
#define NCHUNK (KTOT / 16)       // 34
#define BM    128
#define NTILES (Tt / BM)         // 16

// ---------------- scratch ----------------
__device__ float          g_pqe[Bx * Ux];
__device__ float          g_biasc[Ux];                 // conv_b @ Wle
__device__ __nv_bfloat16  g_Bw[KTOT * Ux];             // [Wm@We(512) ; G(31) ; 0(1)]
__device__ float          g_pA[Bx * NTILES * ENCx];
__device__ float          g_pB[Bx * NTILES * ENCx];
__device__ float          g_pS[Bx * NTILES];
__device__ float          g_pSt[Bx * NTILES];

// ---------------- PTX helpers ----------------
#define LDSM_X4(R, addr) \
    asm volatile("ldmatrix.sync.aligned.m8n8.x4.shared.b16 {%0,%1,%2,%3}, [%4];" \
        : "=r"((R)[0]), "=r"((R)[1]), "=r"((R)[2]), "=r"((R)[3]) : "r"(addr))

#define LDSM_X4T(R, addr) \
    asm volatile("ldmatrix.sync.aligned.m8n8.x4.trans.shared.b16 {%0,%1,%2,%3}, [%4];" \
        : "=r"((R)[0]), "=r"((R)[1]), "=r"((R)[2]), "=r"((R)[3]) : "r"(addr))

#define MMA16816(C, A, b0, b1) \
    asm volatile("mma.sync.aligned.m16n8k16.row.col.f32.bf16.bf16.f32 " \
        "{%0,%1,%2,%3},{%4,%5,%6,%7},{%8,%9},{%0,%1,%2,%3};" \
        : "+f"((C)[0]), "+f"((C)[1]), "+f"((C)[2]), "+f"((C)[3]) \
        : "r"((A)[0]), "r"((A)[1]), "r"((A)[2]), "r"((A)[3]), "r"(b0), "r"(b1))

static __device__ __forceinline__ uint32_t smem_u32(const void* p) {
    return (uint32_t)__cvta_generic_to_shared(p);
}
static __device__ __forceinline__ float tanh_fast(float x) {
    float y; asm("tanh.approx.f32 %0, %1;" : "=f"(y) : "f"(x)); return y;
}

// ---------------- setup kernel: 81 blocks x 256 threads, MLP-16 loads ----------------
// bid 0..63  : wfold 8 rows each of Wm@We -> g_Bw
// bid 64     : Wle = Wl@We, then G = conv_w^T@Wle, biasc = conv_b@Wle
// bid 65..80 : pqe for 4 batches each
__global__ __launch_bounds__(256)
void k_setup(const float* __restrict__ Wm, const float* __restrict__ Wl,
             const float* __restrict__ We, const float* __restrict__ query,
             const float* __restrict__ Wq, const float* __restrict__ bq,
             const float* __restrict__ bl, const float* __restrict__ bm,
             const float* __restrict__ be, const float* __restrict__ conv_w,
             const float* __restrict__ conv_b) {
    __shared__ float sh[8192];           // 32KB, sectioned per branch
    const int bid = blockIdx.x, tid = threadIdx.x;

    if (bid < 64) {
        // ---- Wm@We rows [r0, r0+8), MLP-16 on We ----
        const int r0 = bid * 8;
        float* w_sm = sh;                // [8][256]
        #pragma unroll
        for (int r = 0; r < 8; ++r) w_sm[r * 256 + tid] = Wm[(size_t)(r0 + r) * Ux + tid];
        __syncthreads();
        float acc[8];
        #pragma unroll
        for (int r = 0; r < 8; ++r) acc[r] = 0.f;
        #pragma unroll 1
        for (int v0 = 0; v0 < Ux; v0 += 16) {
            float we[16];
            #pragma unroll
            for (int j = 0; j < 16; ++j) we[j] = We[(size_t)(v0 + j) * Ux + tid];
            #pragma unroll
            for (int j = 0; j < 16; ++j) {
                #pragma unroll
                for (int r = 0; r < 8; ++r)
                    acc[r] = fmaf(w_sm[r * 256 + v0 + j], we[j], acc[r]);
            }
        }
        #pragma unroll
        for (int r = 0; r < 8; ++r)
            g_Bw[(size_t)(r0 + r) * Ux + tid] = __float2bfloat16(acc[r]);
    } else if (bid == 64) {
        // ---- Wle = Wl@We (MLP-8), then G and biasc ----
        float* wl_sm = sh;               // [32][256]
        for (int i = tid; i < FILTx * Ux; i += 256) wl_sm[i] = Wl[i];
        __syncthreads();
        float acc[32];
        #pragma unroll
        for (int f = 0; f < 32; ++f) acc[f] = 0.f;
        #pragma unroll 1
        for (int v0 = 0; v0 < Ux; v0 += 8) {
            float we[8];
            #pragma unroll
            for (int j = 0; j < 8; ++j) we[j] = We[(size_t)(v0 + j) * Ux + tid];
            #pragma unroll
            for (int j = 0; j < 8; ++j) {
                #pragma unroll
                for (int f = 0; f < 32; ++f)
                    acc[f] = fmaf(wl_sm[f * 256 + v0 + j], we[j], acc[f]);
            }
        }
        __syncthreads();
        #pragma unroll
        for (int f = 0; f < 32; ++f) wl_sm[f * 256 + tid] = acc[f];   // now Wle
        __syncthreads();
        #pragma unroll 1
        for (int k = 0; k < KWx; ++k) {
            float g = 0.f;
            #pragma unroll
            for (int f = 0; f < 32; ++f) g = fmaf(conv_w[f * KWx + k], wl_sm[f * 256 + tid], g);
            g_Bw[(size_t)(ENCx + k) * Ux + tid] = __float2bfloat16(g);
        }
        g_Bw[(size_t)(KTOT - 1) * Ux + tid] = __float2bfloat16(0.f);  // pad row
        float bc = 0.f;
        #pragma unroll
        for (int f = 0; f < 32; ++f) bc = fmaf(conv_b[f], wl_sm[f * 256 + tid], bc);
        g_biasc[tid] = bc;
    } else {
        // ---- pqe for batches [b0, b0+4), MLP-16 on Wq and We ----
        const int b0 = (bid - 65) * 4;
        float* q_sm = sh;                // [4][1024]
        float* t_sm = sh + 4 * 1024;     // [4][256]
        #pragma unroll
        for (int j = 0; j < 16; ++j) {
            int idx = j * 256 + tid;     // 4096 loads
            int bb = idx >> 10, h = idx & 1023;
            q_sm[idx] = query[((size_t)(b0 + bb) * 2 + 1) * HIDx + h];
        }
        __syncthreads();
        float a[4];
        #pragma unroll
        for (int j = 0; j < 4; ++j) a[j] = 0.f;
        #pragma unroll 1
        for (int h0 = 0; h0 < HIDx; h0 += 16) {
            float wq[16];
            #pragma unroll
            for (int j = 0; j < 16; ++j) wq[j] = Wq[(size_t)(h0 + j) * Ux + tid];
            #pragma unroll
            for (int j = 0; j < 16; ++j) {
                #pragma unroll
                for (int bb = 0; bb < 4; ++bb)
                    a[bb] = fmaf(q_sm[bb * 1024 + h0 + j], wq[j], a[bb]);
            }
        }
        float base = bq[tid] + bl[tid] + bm[tid];
        #pragma unroll
        for (int bb = 0; bb < 4; ++bb) t_sm[bb * 256 + tid] = a[bb] + base;
        __syncthreads();
        float c[4];
        #pragma unroll
        for (int bb = 0; bb < 4; ++bb) c[bb] = be[tid];
        #pragma unroll 1
        for (int v0 = 0; v0 < Ux; v0 += 16) {
            float we[16];
            #pragma unroll
            for (int j = 0; j < 16; ++j) we[j] = We[(size_t)(v0 + j) * Ux + tid];
            #pragma unroll
            for (int j = 0; j < 16; ++j) {
                #pragma unroll
                for (int bb = 0; bb < 4; ++bb)
                    c[bb] = fmaf(t_sm[bb * 256 + v0 + j], we[j], c[bb]);
            }
        }
        #pragma unroll
        for (int bb = 0; bb < 4; ++bb) g_pqe[(size_t)(b0 + bb) * Ux + tid] = c[bb];
    }
}

// ---------------- main fused kernel ----------------
// Block = (b, 128-row t-tile), 512 threads, 16 warps (4m x 4n), warp = 32 rows x 64 cols.
// K = 34 chunks: 32 from memory, 2 from shifted state windows (conv fold).
__global__ __launch_bounds__(512)
void k_main(const float* __restrict__ memory, const float* __restrict__ state,
            const float* __restrict__ v_a) {
    const int b    = blockIdx.x >> 4;
    const int tile = blockIdx.x & 15;
    const int t0   = tile * BM;

    __shared__ __nv_bfloat16 Asm[2][BM][24];    // [buf][m][k], 48B row stride
    __shared__ __nv_bfloat16 Bsm[2][16][264];   // [buf][k][n], 528B row stride
    __shared__ float pq_sm[Ux], va_sm[Ux];
    __shared__ float s_sm[BM], st_sm[BM];
    __shared__ float se[BM + 32];               // state window [t0-15, t0+BM+16)
    __shared__ float e_red[4][BM];

    const int tid  = threadIdx.x;
    const int lane = tid & 31;
    const int warp = tid >> 5;
    const int wm   = warp >> 2;                 // 0..3 (32 rows each)
    const int wn   = warp & 3;                  // 0..3 (64 cols each)

    if (tid < Ux) {
        pq_sm[tid] = g_pqe[b * Ux + tid] + g_biasc[tid];
        va_sm[tid] = v_a[tid];
    }
    if (tid < BM) st_sm[tid] = state[b * Tt + t0 + tid];
    if (tid < BM + 31) {
        int t = t0 + tid - 15;
        se[tid] = (t >= 0 && t < Tt) ? state[b * Tt + t] : 0.f;
    }

    const float* memb = memory + ((size_t)(b * Tt + t0)) * ENCx;

    const int ar = tid >> 2, ak = (tid & 3) * 4;    // A: float4 per thread (128x16)
    const int br = tid >> 5, bc2 = tid & 31;        // B: uint4 per thread (16x256)

    float acc[16][4];
    #pragma unroll
    for (int i = 0; i < 16; ++i) { acc[i][0]=0.f; acc[i][1]=0.f; acc[i][2]=0.f; acc[i][3]=0.f; }

    // prefetch chunk 0
    float4 aReg = *(const float4*)&memb[(size_t)ar * ENCx + ak];
    uint4  bReg = ((const uint4*)g_Bw)[(size_t)br * 32 + bc2];

    const uint32_t a_addr0 = smem_u32(&Asm[0][wm * 32 + (lane & 15)][(lane >> 4) * 8]);
    const int      a_buf_stride = (int)(sizeof(__nv_bfloat16) * BM * 24);

    #pragma unroll 1
    for (int kt = 0; kt < NCHUNK; ++kt) {
        const int buf = kt & 1;
        // store chunk kt
        __nv_bfloat162 p0 = __float22bfloat162_rn(make_float2(aReg.x, aReg.y));
        __nv_bfloat162 p1 = __float22bfloat162_rn(make_float2(aReg.z, aReg.w));
        *(__nv_bfloat162*)&Asm[buf][ar][ak]     = p0;
        *(__nv_bfloat162*)&Asm[buf][ar][ak + 2] = p1;
        *(uint4*)&Bsm[buf][br][bc2 * 8] = bReg;
        __syncthreads();   // single barrier per chunk (alternating buffers)

        // prefetch chunk kt+1
        const int kn = kt + 1;
        if (kn < ENCx / 16) {
            aReg = *(const float4*)&memb[(size_t)ar * ENCx + kn * 16 + ak];
        } else if (kn < NCHUNK) {
            int kk0 = (kn - ENCx / 16) * 16 + ak;
            aReg.x = se[ar + kk0];     aReg.y = se[ar + kk0 + 1];
            aReg.z = se[ar + kk0 + 2]; aReg.w = se[ar + kk0 + 3];
        }
        if (kn < NCHUNK)
            bReg = ((const uint4*)g_Bw)[(size_t)(kn * 16 + br) * 32 + bc2];

        uint32_t a0[4], a1[4];
        LDSM_X4(a0, a_addr0 + buf * a_buf_stride);
        LDSM_X4(a1, a_addr0 + buf * a_buf_stride + 16 * 48);   // +16 rows
        #pragma unroll
        for (int p = 0; p < 4; ++p) {
            int n0 = wn * 64 + p * 16 + ((lane >> 4) << 3);
            uint32_t bf[4];
            LDSM_X4T(bf, smem_u32(&Bsm[buf][lane & 15][n0]));
            MMA16816(acc[2 * p],         a0, bf[0], bf[1]);
            MMA16816(acc[2 * p + 1],     a0, bf[2], bf[3]);
            MMA16816(acc[8 + 2 * p],     a1, bf[0], bf[1]);
            MMA16816(acc[8 + 2 * p + 1], a1, bf[2], bf[3]);
        }
    }

    // ---- epilogue: tanh (MUFU), v_a dot, per-row energy reduce ----
    #pragma unroll
    for (int mt = 0; mt < 2; ++mt) {
        float e0 = 0.f, e1 = 0.f;
        #pragma unroll
        for (int nt = 0; nt < 8; ++nt) {
            const float* c = acc[mt * 8 + nt];
            int u0 = wn * 64 + nt * 8 + (lane & 3) * 2;
            e0 = fmaf(va_sm[u0],     tanh_fast(c[0] + pq_sm[u0]),     e0);
            e0 = fmaf(va_sm[u0 + 1], tanh_fast(c[1] + pq_sm[u0 + 1]), e0);
            e1 = fmaf(va_sm[u0],     tanh_fast(c[2] + pq_sm[u0]),     e1);
            e1 = fmaf(va_sm[u0 + 1], tanh_fast(c[3] + pq_sm[u0 + 1]), e1);
        }
        e0 += __shfl_xor_sync(0xffffffffu, e0, 1);
        e0 += __shfl_xor_sync(0xffffffffu, e0, 2);
        e1 += __shfl_xor_sync(0xffffffffu, e1, 1);
        e1 += __shfl_xor_sync(0xffffffffu, e1, 2);
        if ((lane & 3) == 0) {
            int row = wm * 32 + mt * 16 + (lane >> 2);
            e_red[wn][row]     = e0;
            e_red[wn][row + 8] = e1;
        }
    }
    __syncthreads();
    if (tid < BM) {
        float E = e_red[0][tid] + e_red[1][tid] + e_red[2][tid] + e_red[3][tid];
        s_sm[tid] = 1.f / (1.f + __expf(-E));
    }
    __syncthreads();

    if (tid < 32) {
        float S  = s_sm[tid]  + s_sm[tid + 32] + s_sm[tid + 64]  + s_sm[tid + 96];
        float St = st_sm[tid] + st_sm[tid + 32] + st_sm[tid + 64] + st_sm[tid + 96];
        #pragma unroll
        for (int off = 16; off > 0; off >>= 1) {
            S  += __shfl_xor_sync(0xffffffffu, S, off);
            St += __shfl_xor_sync(0xffffffffu, St, off);
        }
        if (tid == 0) {
            g_pS[b * NTILES + tile]  = S;
            g_pSt[b * NTILES + tile] = St;
        }
    }

    // ---- weighted memory column sums: 1 column per thread (ENC = 512 = blockDim) ----
    float aA = 0.f, aB = 0.f;
    const float* p = memb + tid;
    #pragma unroll 4
    for (int m = 0; m < BM; ++m) {
        float v = p[(size_t)m * ENCx];
        aA = fmaf(st_sm[m], v, aA);
        aB = fmaf(s_sm[m],  v, aB);
    }
    size_t base = (size_t)(b * NTILES + tile) * ENCx;
    g_pA[base + tid] = aA;
    g_pB[base + tid] = aB;
}

// ---------------- finalize ----------------
__global__ void k_final(const float* __restrict__ Wm, const float* __restrict__ bm,
                        float* __restrict__ out) {
    __shared__ float M[ENCx];
    __shared__ float sS[2];
    int b = blockIdx.x, tid = threadIdx.x;   // 256 threads
    if (tid == 0) {
        float S = 0.f, St = 0.f;
        for (int t = 0; t < NTILES; ++t) { S += g_pS[b * NTILES + t]; St += g_pSt[b * NTILES + t]; }
        sS[0] = S; sS[1] = St;
    }
    __syncthreads();
    float invS = 1.f / sS[0];
    for (int e = tid; e < ENCx; e += 256) {
        float a = 0.f, bb = 0.f;
        #pragma unroll
        for (int t = 0; t < NTILES; ++t) {
            a  += g_pA[(b * NTILES + t) * ENCx + e];
            bb += g_pB[(b * NTILES + t) * ENCx + e];
        }
        M[e] = a + bb * invS;
    }
    __syncthreads();
    float cumsum = sS[1] + 1.f;
    float acc = cumsum * bm[tid];
    #pragma unroll 1
    for (int e0 = 0; e0 < ENCx; e0 += 8) {
        float wv[8];
        #pragma unroll
        for (int j = 0; j < 8; ++j) wv[j] = Wm[(size_t)(e0 + j) * Ux + tid];
        #pragma unroll
        for (int j = 0; j < 8; ++j) acc = fmaf(M[e0 + j], wv[j], acc);
    }
    out[b * Ux + tid] = acc;
}

// ---------------- launch ----------------
extern "C" void kernel_launch(void* const* d_in, const int* in_sizes, int n_in,
                              void* d_out, int out_size) {
    const float* query  = (const float*)d_in[0];
    const float* state  = (const float*)d_in[1];
    const float* memory = (const float*)d_in[2];
    const float* Wq     = (const float*)d_in[3];
    const float* bq     = (const float*)d_in[4];
    const float* Wm     = (const float*)d_in[5];
    const float* bm     = (const float*)d_in[6];
    const float* Wl     = (const float*)d_in[7];
    const float* bl     = (const float*)d_in[8];
    const float* conv_w = (const float*)d_in[9];
    const float* conv_b = (const float*)d_in[10];
    const float* We     = (const float*)d_in[11];
    const float* be     = (const float*)d_in[12];
    const float* v_a    = (const float*)d_in[13];
    float* out = (float*)d_out;

    k_setup<<<81, 256>>>(Wm, Wl, We, query, Wq, bq, bl, bm, be, conv_w, conv_b);
    k_main<<<Bx * NTILES, 512>>>(memory, state, v_a);
    k_final<<<Bx, Ux>>>(Wm, bm, out);
}

// round 10
// speedup vs baseline: 3.7639x; 1.0060x over previous
#include <cuda_runtime.h>
#include <cuda_bf16.h>
#include <math.h>
#include <stdint.h>

// Problem constants
#define Bx    64
#define Tt    2048
#define HIDx  1024
#define ENCx  512
#define Ux    256
#define FILTx 32
#define KWx   31
#define KTOT  (ENCx + FILTx)     // 544 = 512 mem-k + 31 conv-k + 1 pad
#define BK    32
#define NCH   (KTOT / BK)        // 17
#define BM    128
#define NTILES (Tt / BM)         // 16
#define NSTAGE 4

// ---------------- scratch ----------------
__device__ float g_pqe[Bx * Ux];
__device__ float g_biasc[Ux];                       // conv_b @ Wle
__device__ float g_pqp[4 * Bx * Ux];                // split-K pq partials
__device__ __align__(128) __nv_bfloat16 g_Bw[KTOT * Ux];   // [Wm@We(512); G(31); 0]
__device__ float g_pA[Bx * NTILES * ENCx];
__device__ float g_pB[Bx * NTILES * ENCx];
__device__ float g_pS[Bx * NTILES];
__device__ float g_pSt[Bx * NTILES];

// ---------------- smem layout (bytes) ----------------
#define AST_STRIDE (128 * 36 * 4)        // [128][36] fp32 per stage (padded)
#define BST_STRIDE (32 * 264 * 2)        // [32][264] bf16 per stage (padded)
#define AST_OFF 0
#define BST_OFF (AST_OFF + NSTAGE * AST_STRIDE)          // 73728
#define PQ_OFF  (BST_OFF + NSTAGE * BST_STRIDE)          // 141312
#define VA_OFF  (PQ_OFF + 1024)
#define S_OFF   (VA_OFF + 1024)
#define ST_OFF  (S_OFF + 512)
#define SE_OFF  (ST_OFF + 512)                           // 192 floats
#define ER_OFF  (SE_OFF + 768)
#define SM_TOTAL (ER_OFF + 2048)                         // ~147KB

// ---------------- PTX helpers ----------------
#define LDSM_X4T(R, addr) \
    asm volatile("ldmatrix.sync.aligned.m8n8.x4.trans.shared.b16 {%0,%1,%2,%3}, [%4];" \
        : "=r"((R)[0]), "=r"((R)[1]), "=r"((R)[2]), "=r"((R)[3]) : "r"(addr))

#define MMA16816(C, A, b0, b1) \
    asm volatile("mma.sync.aligned.m16n8k16.row.col.f32.bf16.bf16.f32 " \
        "{%0,%1,%2,%3},{%4,%5,%6,%7},{%8,%9},{%0,%1,%2,%3};" \
        : "+f"((C)[0]), "+f"((C)[1]), "+f"((C)[2]), "+f"((C)[3]) \
        : "r"((A)[0]), "r"((A)[1]), "r"((A)[2]), "r"((A)[3]), "r"(b0), "r"(b1))

#define CP16(dst, src) \
    asm volatile("cp.async.cg.shared.global [%0], [%1], 16;" :: "r"(dst), "l"(src))
#define CP_COMMIT() asm volatile("cp.async.commit_group;" ::: "memory")
#define CP_WAIT2()  asm volatile("cp.async.wait_group 2;" ::: "memory")

static __device__ __forceinline__ uint32_t smem_u32(const void* p) {
    return (uint32_t)__cvta_generic_to_shared(p);
}
static __device__ __forceinline__ float tanh_fast(float x) {
    float y; asm("tanh.approx.f32 %0, %1;" : "=f"(y) : "f"(x)); return y;
}
static __device__ __forceinline__ uint32_t packbf(float x, float y) {
    __nv_bfloat162 h = __float22bfloat162_rn(make_float2(x, y));
    return *(uint32_t*)&h;
}

// ---------------- setup1: wfold + Wle/G/biasc + pq split-K partials ----------------
__global__ __launch_bounds__(256)
void k_setup1(const float* __restrict__ Wm, const float* __restrict__ Wl,
              const float* __restrict__ We, const float* __restrict__ query,
              const float* __restrict__ Wq, const float* __restrict__ conv_w,
              const float* __restrict__ conv_b) {
    __shared__ float sh[8192];
    const int bid = blockIdx.x, tid = threadIdx.x;

    if (bid < 64) {
        const int r0 = bid * 8;
        float* w_sm = sh;
        #pragma unroll
        for (int r = 0; r < 8; ++r) w_sm[r * 256 + tid] = Wm[(size_t)(r0 + r) * Ux + tid];
        __syncthreads();
        float acc[8];
        #pragma unroll
        for (int r = 0; r < 8; ++r) acc[r] = 0.f;
        #pragma unroll 1
        for (int v0 = 0; v0 < Ux; v0 += 16) {
            float we[16];
            #pragma unroll
            for (int j = 0; j < 16; ++j) we[j] = We[(size_t)(v0 + j) * Ux + tid];
            #pragma unroll
            for (int j = 0; j < 16; ++j)
                #pragma unroll
                for (int r = 0; r < 8; ++r)
                    acc[r] = fmaf(w_sm[r * 256 + v0 + j], we[j], acc[r]);
        }
        #pragma unroll
        for (int r = 0; r < 8; ++r)
            g_Bw[(size_t)(r0 + r) * Ux + tid] = __float2bfloat16(acc[r]);
    } else if (bid == 64) {
        float* wl_sm = sh;               // [32][256]
        for (int i = tid; i < FILTx * Ux; i += 256) wl_sm[i] = Wl[i];
        __syncthreads();
        float acc[32];
        #pragma unroll
        for (int f = 0; f < 32; ++f) acc[f] = 0.f;
        #pragma unroll 1
        for (int v0 = 0; v0 < Ux; v0 += 8) {
            float we[8];
            #pragma unroll
            for (int j = 0; j < 8; ++j) we[j] = We[(size_t)(v0 + j) * Ux + tid];
            #pragma unroll
            for (int j = 0; j < 8; ++j)
                #pragma unroll
                for (int f = 0; f < 32; ++f)
                    acc[f] = fmaf(wl_sm[f * 256 + v0 + j], we[j], acc[f]);
        }
        __syncthreads();
        #pragma unroll
        for (int f = 0; f < 32; ++f) wl_sm[f * 256 + tid] = acc[f];   // now Wle
        __syncthreads();
        #pragma unroll 1
        for (int k = 0; k < KWx; ++k) {
            float g = 0.f;
            #pragma unroll
            for (int f = 0; f < 32; ++f) g = fmaf(conv_w[f * KWx + k], wl_sm[f * 256 + tid], g);
            g_Bw[(size_t)(ENCx + k) * Ux + tid] = __float2bfloat16(g);
        }
        g_Bw[(size_t)(KTOT - 1) * Ux + tid] = __float2bfloat16(0.f);  // pad row
        float bc = 0.f;
        #pragma unroll
        for (int f = 0; f < 32; ++f) bc = fmaf(conv_b[f], wl_sm[f * 256 + tid], bc);
        g_biasc[tid] = bc;
    } else {
        const int i = bid - 65;
        const int b0 = (i >> 2) * 4;
        const int h0 = (i & 3) * 256;
        float* q_sm = sh;                // [4][256]
        #pragma unroll
        for (int j = 0; j < 4; ++j) {
            int idx = j * 256 + tid;
            int bb = idx >> 8, h = idx & 255;
            q_sm[idx] = query[((size_t)(b0 + bb) * 2 + 1) * HIDx + h0 + h];
        }
        __syncthreads();
        float a[4];
        #pragma unroll
        for (int j = 0; j < 4; ++j) a[j] = 0.f;
        #pragma unroll 1
        for (int v0 = 0; v0 < 256; v0 += 16) {
            float wq[16];
            #pragma unroll
            for (int j = 0; j < 16; ++j) wq[j] = Wq[(size_t)(h0 + v0 + j) * Ux + tid];
            #pragma unroll
            for (int j = 0; j < 16; ++j)
                #pragma unroll
                for (int bb = 0; bb < 4; ++bb)
                    a[bb] = fmaf(q_sm[bb * 256 + v0 + j], wq[j], a[bb]);
        }
        #pragma unroll
        for (int bb = 0; bb < 4; ++bb)
            g_pqp[((size_t)(i & 3) * Bx + b0 + bb) * Ux + tid] = a[bb];
    }
}

// ---------------- setup2: combine pq partials, @We, + be ----------------
__global__ __launch_bounds__(256)
void k_setup2(const float* __restrict__ bq, const float* __restrict__ bl,
              const float* __restrict__ bm, const float* __restrict__ We,
              const float* __restrict__ be) {
    __shared__ float t_sm[4][256];
    const int b0 = blockIdx.x * 4, tid = threadIdx.x;
    float base = bq[tid] + bl[tid] + bm[tid];
    #pragma unroll
    for (int bb = 0; bb < 4; ++bb) {
        float t = base;
        #pragma unroll
        for (int s = 0; s < 4; ++s) t += g_pqp[((size_t)s * Bx + b0 + bb) * Ux + tid];
        t_sm[bb][tid] = t;
    }
    __syncthreads();
    float c[4];
    #pragma unroll
    for (int bb = 0; bb < 4; ++bb) c[bb] = be[tid];
    #pragma unroll 1
    for (int v0 = 0; v0 < Ux; v0 += 16) {
        float we[16];
        #pragma unroll
        for (int j = 0; j < 16; ++j) we[j] = We[(size_t)(v0 + j) * Ux + tid];
        #pragma unroll
        for (int j = 0; j < 16; ++j)
            #pragma unroll
            for (int bb = 0; bb < 4; ++bb)
                c[bb] = fmaf(t_sm[bb][v0 + j], we[j], c[bb]);
    }
    #pragma unroll
    for (int bb = 0; bb < 4; ++bb) g_pqe[(size_t)(b0 + bb) * Ux + tid] = c[bb];
}

// ---------------- main: cp.async 4-stage pipeline + mma.sync ----------------
// Block = (b, 128-row t-tile), 512 threads, 16 warps (4m x 4n), warp = 32m x 64n.
__global__ __launch_bounds__(512, 1)
void k_main(const float* __restrict__ memory, const float* __restrict__ state,
            const float* __restrict__ v_a) {
    extern __shared__ char smem[];
    const int b    = blockIdx.x >> 4;
    const int tile = blockIdx.x & 15;
    const int t0   = tile * BM;
    const int tid  = threadIdx.x;
    const int lane = tid & 31;
    const int warp = tid >> 5;
    const int wm   = warp >> 2;                 // 0..3 (32 rows each)
    const int wn   = warp & 3;                  // 0..3 (64 cols each)

    float* pq_sm = (float*)(smem + PQ_OFF);
    float* va_sm = (float*)(smem + VA_OFF);
    float* s_sm  = (float*)(smem + S_OFF);
    float* st_sm = (float*)(smem + ST_OFF);
    float* se    = (float*)(smem + SE_OFF);
    float* e_red = (float*)(smem + ER_OFF);     // [4][128]

    if (tid < Ux) {
        pq_sm[tid] = g_pqe[b * Ux + tid] + g_biasc[tid];
        va_sm[tid] = v_a[tid];
    }
    if (tid < BM) st_sm[tid] = state[b * Tt + t0 + tid];
    if (tid < 192) {
        int t = t0 + tid - 15;
        se[tid] = (t >= 0 && t < Tt) ? state[b * Tt + t] : 0.f;
    }

    const char* membp = (const char*)(memory + ((size_t)(b * Tt + t0)) * ENCx);
    const char* bwp   = (const char*)g_Bw;
    const uint32_t smb = smem_u32(smem);

    // copy chunk c into stage: A = 128x32 fp32 (skip for c==16), B = 32x256 bf16
    auto copy_chunk = [&](int c, int stage) {
        if (c < 16) {
            #pragma unroll
            for (int j = 0; j < 2; ++j) {
                int u = j * 512 + tid;           // 1024 16B units (128 rows x 8)
                int row = u >> 3, c4 = u & 7;
                uint32_t dst = smb + AST_OFF + stage * AST_STRIDE + row * 144 + c4 * 16;
                const char* src = membp + (size_t)row * 2048 + c * 128 + c4 * 16;
                CP16(dst, src);
            }
        }
        #pragma unroll
        for (int j = 0; j < 2; ++j) {
            int u = j * 512 + tid;               // 1024 16B units (32 rows x 32)
            int row = u >> 5, c16 = u & 31;      // FIXED: 512B per B row
            uint32_t dst = smb + BST_OFF + stage * BST_STRIDE + row * 528 + c16 * 16;
            const char* src = bwp + (size_t)(c * 32 + row) * 512 + c16 * 16;
            CP16(dst, src);
        }
    };

    __syncthreads();                             // se visible before any use

    // prologue: stages 0..2
    copy_chunk(0, 0); CP_COMMIT();
    copy_chunk(1, 1); CP_COMMIT();
    copy_chunk(2, 2); CP_COMMIT();

    float acc[16][4];
    #pragma unroll
    for (int i = 0; i < 16; ++i) { acc[i][0]=0.f; acc[i][1]=0.f; acc[i][2]=0.f; acc[i][3]=0.f; }

    const int kf = (lane & 3) * 2;
    const int arow = (lane >> 2);

    #pragma unroll 1
    for (int c = 0; c < NCH; ++c) {
        const int stage = c & 3;
        CP_WAIT2();                              // chunk c's group complete
        __syncthreads();                         // cross-thread visibility; gates stage reuse

        if (c + 3 < NCH) copy_chunk(c + 3, (c + 3) & 3);
        CP_COMMIT();                             // commit (possibly empty) every iter

        const float* Ast = (const float*)(smem + AST_OFF + stage * AST_STRIDE);
        const uint32_t bst = smb + BST_OFF + stage * BST_STRIDE;

        #pragma unroll
        for (int ks = 0; ks < 2; ++ks) {
            uint32_t a0[4], a1[4];
            if (c < 16) {
                #pragma unroll
                for (int sub = 0; sub < 2; ++sub) {
                    const float* base0 = Ast + (size_t)(wm * 32 + sub * 16 + arow) * 36 + ks * 16 + kf;
                    float2 f01 = *(const float2*)(base0);
                    float2 f23 = *(const float2*)(base0 + 8 * 36);
                    float2 f45 = *(const float2*)(base0 + 8);
                    float2 f67 = *(const float2*)(base0 + 8 * 36 + 8);
                    uint32_t* A = sub ? a1 : a0;
                    A[0] = packbf(f01.x, f01.y);
                    A[1] = packbf(f23.x, f23.y);
                    A[2] = packbf(f45.x, f45.y);
                    A[3] = packbf(f67.x, f67.y);
                }
            } else {
                #pragma unroll
                for (int sub = 0; sub < 2; ++sub) {
                    int row = wm * 32 + sub * 16 + arow;
                    int kk = ks * 16 + kf;
                    float v0 = (kk     < KWx) ? se[row + kk]         : 0.f;
                    float v1 = (kk + 1 < KWx) ? se[row + kk + 1]     : 0.f;
                    float v2 = (kk     < KWx) ? se[row + 8 + kk]     : 0.f;
                    float v3 = (kk + 1 < KWx) ? se[row + 8 + kk + 1] : 0.f;
                    float v4 = (kk + 8 < KWx) ? se[row + kk + 8]     : 0.f;
                    float v5 = (kk + 9 < KWx) ? se[row + kk + 9]     : 0.f;
                    float v6 = (kk + 8 < KWx) ? se[row + 8 + kk + 8] : 0.f;
                    float v7 = (kk + 9 < KWx) ? se[row + 8 + kk + 9] : 0.f;
                    uint32_t* A = sub ? a1 : a0;
                    A[0] = packbf(v0, v1);
                    A[1] = packbf(v2, v3);
                    A[2] = packbf(v4, v5);
                    A[3] = packbf(v6, v7);
                }
            }
            #pragma unroll
            for (int p = 0; p < 4; ++p) {
                uint32_t bf[4];
                uint32_t baddr = bst + (uint32_t)(ks * 16 + (lane & 15)) * 528
                               + (uint32_t)(wn * 64 + p * 16 + ((lane >> 4) << 3)) * 2;
                LDSM_X4T(bf, baddr);
                MMA16816(acc[2 * p],         a0, bf[0], bf[1]);
                MMA16816(acc[2 * p + 1],     a0, bf[2], bf[3]);
                MMA16816(acc[8 + 2 * p],     a1, bf[0], bf[1]);
                MMA16816(acc[8 + 2 * p + 1], a1, bf[2], bf[3]);
            }
        }
    }

    // ---- epilogue: tanh (MUFU), v_a dot, per-row energy reduce ----
    #pragma unroll
    for (int mt = 0; mt < 2; ++mt) {
        float e0 = 0.f, e1 = 0.f;
        #pragma unroll
        for (int nt = 0; nt < 8; ++nt) {
            const float* cc = acc[mt * 8 + nt];
            int u0 = wn * 64 + nt * 8 + (lane & 3) * 2;
            e0 = fmaf(va_sm[u0],     tanh_fast(cc[0] + pq_sm[u0]),     e0);
            e0 = fmaf(va_sm[u0 + 1], tanh_fast(cc[1] + pq_sm[u0 + 1]), e0);
            e1 = fmaf(va_sm[u0],     tanh_fast(cc[2] + pq_sm[u0]),     e1);
            e1 = fmaf(va_sm[u0 + 1], tanh_fast(cc[3] + pq_sm[u0 + 1]), e1);
        }
        e0 += __shfl_xor_sync(0xffffffffu, e0, 1);
        e0 += __shfl_xor_sync(0xffffffffu, e0, 2);
        e1 += __shfl_xor_sync(0xffffffffu, e1, 1);
        e1 += __shfl_xor_sync(0xffffffffu, e1, 2);
        if ((lane & 3) == 0) {
            int row = wm * 32 + mt * 16 + (lane >> 2);
            e_red[wn * 128 + row]     = e0;
            e_red[wn * 128 + row + 8] = e1;
        }
    }
    __syncthreads();
    if (tid < BM) {
        float E = e_red[tid] + e_red[128 + tid] + e_red[256 + tid] + e_red[384 + tid];
        s_sm[tid] = 1.f / (1.f + __expf(-E));
    }
    __syncthreads();

    if (tid < 32) {
        float S  = s_sm[tid]  + s_sm[tid + 32]  + s_sm[tid + 64]  + s_sm[tid + 96];
        float St = st_sm[tid] + st_sm[tid + 32] + st_sm[tid + 64] + st_sm[tid + 96];
        #pragma unroll
        for (int off = 16; off > 0; off >>= 1) {
            S  += __shfl_xor_sync(0xffffffffu, S, off);
            St += __shfl_xor_sync(0xffffffffu, St, off);
        }
        if (tid == 0) {
            g_pS[b * NTILES + tile]  = S;
            g_pSt[b * NTILES + tile] = St;
        }
    }

    // ---- weighted memory column sums: 1 column per thread ----
    float aA = 0.f, aB = 0.f;
    const float* memf = (const float*)membp;
    const float* p = memf + tid;
    #pragma unroll 4
    for (int m = 0; m < BM; ++m) {
        float v = p[(size_t)m * ENCx];
        aA = fmaf(st_sm[m], v, aA);
        aB = fmaf(s_sm[m],  v, aB);
    }
    size_t base = (size_t)(b * NTILES + tile) * ENCx;
    g_pA[base + tid] = aA;
    g_pB[base + tid] = aB;
}

// ---------------- finalize ----------------
__global__ void k_final(const float* __restrict__ Wm, const float* __restrict__ bm,
                        float* __restrict__ out) {
    __shared__ float M[ENCx];
    __shared__ float sS[2];
    int b = blockIdx.x, tid = threadIdx.x;   // 256 threads
    if (tid == 0) {
        float S = 0.f, St = 0.f;
        for (int t = 0; t < NTILES; ++t) { S += g_pS[b * NTILES + t]; St += g_pSt[b * NTILES + t]; }
        sS[0] = S; sS[1] = St;
    }
    __syncthreads();
    float invS = 1.f / sS[0];
    for (int e = tid; e < ENCx; e += 256) {
        float a = 0.f, bb = 0.f;
        #pragma unroll
        for (int t = 0; t < NTILES; ++t) {
            a  += g_pA[(b * NTILES + t) * ENCx + e];
            bb += g_pB[(b * NTILES + t) * ENCx + e];
        }
        M[e] = a + bb * invS;
    }
    __syncthreads();
    float cumsum = sS[1] + 1.f;
    float acc = cumsum * bm[tid];
    #pragma unroll 1
    for (int e0 = 0; e0 < ENCx; e0 += 8) {
        float wv[8];
        #pragma unroll
        for (int j = 0; j < 8; ++j) wv[j] = Wm[(size_t)(e0 + j) * Ux + tid];
        #pragma unroll
        for (int j = 0; j < 8; ++j) acc = fmaf(M[e0 + j], wv[j], acc);
    }
    out[b * Ux + tid] = acc;
}

// ---------------- launch ----------------
extern "C" void kernel_launch(void* const* d_in, const int* in_sizes, int n_in,
                              void* d_out, int out_size) {
    const float* query  = (const float*)d_in[0];
    const float* state  = (const float*)d_in[1];
    const float* memory = (const float*)d_in[2];
    const float* Wq     = (const float*)d_in[3];
    const float* bq     = (const float*)d_in[4];
    const float* Wm     = (const float*)d_in[5];
    const float* bm     = (const float*)d_in[6];
    const float* Wl     = (const float*)d_in[7];
    const float* bl     = (const float*)d_in[8];
    const float* conv_w = (const float*)d_in[9];
    const float* conv_b = (const float*)d_in[10];
    const float* We     = (const float*)d_in[11];
    const float* be     = (const float*)d_in[12];
    const float* v_a    = (const float*)d_in[13];
    float* out = (float*)d_out;

    cudaFuncSetAttribute(k_main, cudaFuncAttributeMaxDynamicSharedMemorySize, SM_TOTAL);

    k_setup1<<<129, 256>>>(Wm, Wl, We, query, Wq, conv_w, conv_b);
    k_setup2<<<16, 256>>>(bq, bl, bm, We, be);
    k_main<<<Bx * NTILES, 512, SM_TOTAL>>>(memory, state, v_a);
    k_final<<<Bx, Ux>>>(Wm, bm, out);
}

// round 11
// speedup vs baseline: 4.4979x; 1.1950x over previous
#include <cuda_runtime.h>
#include <cuda_bf16.h>
#include <math.h>
#include <stdint.h>

// Problem constants
#define Bx    64
#define Tt    2048
#define HIDx  1024
#define ENCx  512
#define Ux    256
#define FILTx 32
#define KWx   31
#define KTOT  (ENCx + FILTx)     // 544 = 512 mem-k + 31 conv-k + 1 pad
#define BK    32
#define NCH   (KTOT / BK)        // 17
#define BM    128
#define NTILES (Tt / BM)         // 16
#define NSTAGE 4

// ---------------- scratch ----------------
__device__ float g_pqe[Bx * Ux];
__device__ float g_biasc[Ux];                       // conv_b @ Wle
__device__ float g_pqp[4 * Bx * Ux];                // split-K pq partials
__device__ __align__(128) __nv_bfloat16 g_Bw[KTOT * Ux];   // [Wm@We(512); G(31); 0]
__device__ float g_pA[Bx * NTILES * ENCx];
__device__ float g_pB[Bx * NTILES * ENCx];
__device__ float g_pS[Bx * NTILES];
__device__ float g_pSt[Bx * NTILES];

// ---------------- smem layout (bytes) ----------------
#define BST_STRIDE (32 * 264 * 2)        // [32][264] bf16 per stage
#define BST_OFF 0
#define ABUF_STRIDE (128 * 40 * 2)       // [128][40] bf16 per buffer (80B rows)
#define ABUF_OFF (BST_OFF + NSTAGE * BST_STRIDE)         // 67584
#define PQ_OFF  (ABUF_OFF + 2 * ABUF_STRIDE)             // 88064
#define VA_OFF  (PQ_OFF + 1024)
#define S_OFF   (VA_OFF + 1024)
#define ST_OFF  (S_OFF + 512)
#define SE_OFF  (ST_OFF + 512)                           // 192 floats
#define ER_OFF  (SE_OFF + 768)
#define SM_TOTAL (ER_OFF + 2048)                         // ~94KB

// ---------------- PTX helpers ----------------
#define LDSM_X4(R, addr) \
    asm volatile("ldmatrix.sync.aligned.m8n8.x4.shared.b16 {%0,%1,%2,%3}, [%4];" \
        : "=r"((R)[0]), "=r"((R)[1]), "=r"((R)[2]), "=r"((R)[3]) : "r"(addr))

#define LDSM_X4T(R, addr) \
    asm volatile("ldmatrix.sync.aligned.m8n8.x4.trans.shared.b16 {%0,%1,%2,%3}, [%4];" \
        : "=r"((R)[0]), "=r"((R)[1]), "=r"((R)[2]), "=r"((R)[3]) : "r"(addr))

#define MMA16816(C, A, b0, b1) \
    asm volatile("mma.sync.aligned.m16n8k16.row.col.f32.bf16.bf16.f32 " \
        "{%0,%1,%2,%3},{%4,%5,%6,%7},{%8,%9},{%0,%1,%2,%3};" \
        : "+f"((C)[0]), "+f"((C)[1]), "+f"((C)[2]), "+f"((C)[3]) \
        : "r"((A)[0]), "r"((A)[1]), "r"((A)[2]), "r"((A)[3]), "r"(b0), "r"(b1))

#define CP16(dst, src) \
    asm volatile("cp.async.cg.shared.global [%0], [%1], 16;" :: "r"(dst), "l"(src))
#define CP_COMMIT() asm volatile("cp.async.commit_group;" ::: "memory")
#define CP_WAIT2()  asm volatile("cp.async.wait_group 2;" ::: "memory")

static __device__ __forceinline__ uint32_t smem_u32(const void* p) {
    return (uint32_t)__cvta_generic_to_shared(p);
}
static __device__ __forceinline__ float tanh_fast(float x) {
    float y; asm("tanh.approx.f32 %0, %1;" : "=f"(y) : "f"(x)); return y;
}
static __device__ __forceinline__ uint32_t packbf(float x, float y) {
    __nv_bfloat162 h = __float22bfloat162_rn(make_float2(x, y));
    return *(uint32_t*)&h;
}

// ---------------- setup1: wfold + Wle/G/biasc + pq split-K partials ----------------
__global__ __launch_bounds__(256)
void k_setup1(const float* __restrict__ Wm, const float* __restrict__ Wl,
              const float* __restrict__ We, const float* __restrict__ query,
              const float* __restrict__ Wq, const float* __restrict__ conv_w,
              const float* __restrict__ conv_b) {
    __shared__ float sh[8192];
    const int bid = blockIdx.x, tid = threadIdx.x;

    if (bid < 64) {
        const int r0 = bid * 8;
        float* w_sm = sh;
        #pragma unroll
        for (int r = 0; r < 8; ++r) w_sm[r * 256 + tid] = Wm[(size_t)(r0 + r) * Ux + tid];
        __syncthreads();
        float acc[8];
        #pragma unroll
        for (int r = 0; r < 8; ++r) acc[r] = 0.f;
        #pragma unroll 1
        for (int v0 = 0; v0 < Ux; v0 += 16) {
            float we[16];
            #pragma unroll
            for (int j = 0; j < 16; ++j) we[j] = We[(size_t)(v0 + j) * Ux + tid];
            #pragma unroll
            for (int j = 0; j < 16; ++j)
                #pragma unroll
                for (int r = 0; r < 8; ++r)
                    acc[r] = fmaf(w_sm[r * 256 + v0 + j], we[j], acc[r]);
        }
        #pragma unroll
        for (int r = 0; r < 8; ++r)
            g_Bw[(size_t)(r0 + r) * Ux + tid] = __float2bfloat16(acc[r]);
    } else if (bid == 64) {
        float* wl_sm = sh;               // [32][256]
        for (int i = tid; i < FILTx * Ux; i += 256) wl_sm[i] = Wl[i];
        __syncthreads();
        float acc[32];
        #pragma unroll
        for (int f = 0; f < 32; ++f) acc[f] = 0.f;
        #pragma unroll 1
        for (int v0 = 0; v0 < Ux; v0 += 8) {
            float we[8];
            #pragma unroll
            for (int j = 0; j < 8; ++j) we[j] = We[(size_t)(v0 + j) * Ux + tid];
            #pragma unroll
            for (int j = 0; j < 8; ++j)
                #pragma unroll
                for (int f = 0; f < 32; ++f)
                    acc[f] = fmaf(wl_sm[f * 256 + v0 + j], we[j], acc[f]);
        }
        __syncthreads();
        #pragma unroll
        for (int f = 0; f < 32; ++f) wl_sm[f * 256 + tid] = acc[f];   // now Wle
        __syncthreads();
        #pragma unroll 1
        for (int k = 0; k < KWx; ++k) {
            float g = 0.f;
            #pragma unroll
            for (int f = 0; f < 32; ++f) g = fmaf(conv_w[f * KWx + k], wl_sm[f * 256 + tid], g);
            g_Bw[(size_t)(ENCx + k) * Ux + tid] = __float2bfloat16(g);
        }
        g_Bw[(size_t)(KTOT - 1) * Ux + tid] = __float2bfloat16(0.f);  // pad row
        float bc = 0.f;
        #pragma unroll
        for (int f = 0; f < 32; ++f) bc = fmaf(conv_b[f], wl_sm[f * 256 + tid], bc);
        g_biasc[tid] = bc;
    } else {
        const int i = bid - 65;
        const int b0 = (i >> 2) * 4;
        const int h0 = (i & 3) * 256;
        float* q_sm = sh;                // [4][256]
        #pragma unroll
        for (int j = 0; j < 4; ++j) {
            int idx = j * 256 + tid;
            int bb = idx >> 8, h = idx & 255;
            q_sm[idx] = query[((size_t)(b0 + bb) * 2 + 1) * HIDx + h0 + h];
        }
        __syncthreads();
        float a[4];
        #pragma unroll
        for (int j = 0; j < 4; ++j) a[j] = 0.f;
        #pragma unroll 1
        for (int v0 = 0; v0 < 256; v0 += 16) {
            float wq[16];
            #pragma unroll
            for (int j = 0; j < 16; ++j) wq[j] = Wq[(size_t)(h0 + v0 + j) * Ux + tid];
            #pragma unroll
            for (int j = 0; j < 16; ++j)
                #pragma unroll
                for (int bb = 0; bb < 4; ++bb)
                    a[bb] = fmaf(q_sm[bb * 256 + v0 + j], wq[j], a[bb]);
        }
        #pragma unroll
        for (int bb = 0; bb < 4; ++bb)
            g_pqp[((size_t)(i & 3) * Bx + b0 + bb) * Ux + tid] = a[bb];
    }
}

// ---------------- setup2: combine pq partials, @We, + be ----------------
__global__ __launch_bounds__(256)
void k_setup2(const float* __restrict__ bq, const float* __restrict__ bl,
              const float* __restrict__ bm, const float* __restrict__ We,
              const float* __restrict__ be) {
    __shared__ float t_sm[4][256];
    const int b0 = blockIdx.x * 4, tid = threadIdx.x;
    float base = bq[tid] + bl[tid] + bm[tid];
    #pragma unroll
    for (int bb = 0; bb < 4; ++bb) {
        float t = base;
        #pragma unroll
        for (int s = 0; s < 4; ++s) t += g_pqp[((size_t)s * Bx + b0 + bb) * Ux + tid];
        t_sm[bb][tid] = t;
    }
    __syncthreads();
    float c[4];
    #pragma unroll
    for (int bb = 0; bb < 4; ++bb) c[bb] = be[tid];
    #pragma unroll 1
    for (int v0 = 0; v0 < Ux; v0 += 16) {
        float we[16];
        #pragma unroll
        for (int j = 0; j < 16; ++j) we[j] = We[(size_t)(v0 + j) * Ux + tid];
        #pragma unroll
        for (int j = 0; j < 16; ++j)
            #pragma unroll
            for (int bb = 0; bb < 4; ++bb)
                c[bb] = fmaf(t_sm[bb][v0 + j], we[j], c[bb]);
    }
    #pragma unroll
    for (int bb = 0; bb < 4; ++bb) g_pqe[(size_t)(b0 + bb) * Ux + tid] = c[bb];
}

// ---------------- main: B via cp.async, A via register prefetch + bf16 smem ----------------
// Block = (b, 128-row t-tile), 512 threads, 16 warps (4m x 4n), warp = 32m x 64n.
__global__ __launch_bounds__(512, 1)
void k_main(const float* __restrict__ memory, const float* __restrict__ state,
            const float* __restrict__ v_a) {
    extern __shared__ char smem[];
    const int b    = blockIdx.x >> 4;
    const int tile = blockIdx.x & 15;
    const int t0   = tile * BM;
    const int tid  = threadIdx.x;
    const int lane = tid & 31;
    const int warp = tid >> 5;
    const int wm   = warp >> 2;                 // 0..3 (32 rows each)
    const int wn   = warp & 3;                  // 0..3 (64 cols each)

    float* pq_sm = (float*)(smem + PQ_OFF);
    float* va_sm = (float*)(smem + VA_OFF);
    float* s_sm  = (float*)(smem + S_OFF);
    float* st_sm = (float*)(smem + ST_OFF);
    float* se    = (float*)(smem + SE_OFF);
    float* e_red = (float*)(smem + ER_OFF);     // [4][128]

    if (tid < Ux) {
        pq_sm[tid] = g_pqe[b * Ux + tid] + g_biasc[tid];
        va_sm[tid] = v_a[tid];
    }
    if (tid < BM) st_sm[tid] = state[b * Tt + t0 + tid];
    if (tid < 192) {
        int t = t0 + tid - 15;
        se[tid] = (t >= 0 && t < Tt) ? state[b * Tt + t] : 0.f;
    }

    const float* memb = memory + ((size_t)(b * Tt + t0)) * ENCx;
    const char*  bwp  = (const char*)g_Bw;
    const uint32_t smb = smem_u32(smem);

    // A load indices: 1024 float4 per chunk, 2 per thread
    const int ar0 = tid >> 2,         ac0 = (tid & 3);            // j=0: rows 0..127
    const int ar1 = (512 + tid) >> 3, ac1 = (512 + tid) & 7;      // (recomputed properly below)
    // (use uniform formula: u = j*512+tid; row=u>>3; c4=u&7)

    // B copy: chunk c -> stage
    auto copyB = [&](int c, int stage) {
        #pragma unroll
        for (int j = 0; j < 2; ++j) {
            int u = j * 512 + tid;               // 1024 16B units (32 rows x 32)
            int row = u >> 5, c16 = u & 31;
            uint32_t dst = smb + BST_OFF + stage * BST_STRIDE + row * 528 + c16 * 16;
            const char* src = bwp + (size_t)(c * 32 + row) * 512 + c16 * 16;
            CP16(dst, src);
        }
    };

    __syncthreads();                             // se/st/pq visible

    copyB(0, 0); CP_COMMIT();
    copyB(1, 1); CP_COMMIT();
    copyB(2, 2); CP_COMMIT();

    // prefetch A chunk 0 to registers
    float4 aReg[2];
    #pragma unroll
    for (int j = 0; j < 2; ++j) {
        int u = j * 512 + tid, row = u >> 3, c4 = u & 7;
        aReg[j] = *(const float4*)&memb[(size_t)row * ENCx + c4 * 4];
    }

    float acc[16][4];
    #pragma unroll
    for (int i = 0; i < 16; ++i) { acc[i][0]=0.f; acc[i][1]=0.f; acc[i][2]=0.f; acc[i][3]=0.f; }

    #pragma unroll 1
    for (int c = 0; c < NCH; ++c) {
        const int stage = c & 3;
        const int abuf  = c & 1;
        char* Ab = smem + ABUF_OFF + abuf * ABUF_STRIDE;

        // store A chunk c (bf16) into Ab
        if (c < 16) {
            #pragma unroll
            for (int j = 0; j < 2; ++j) {
                int u = j * 512 + tid, row = u >> 3, c4 = u & 7;
                uint2 pk;
                pk.x = packbf(aReg[j].x, aReg[j].y);
                pk.y = packbf(aReg[j].z, aReg[j].w);
                *(uint2*)(Ab + row * 80 + c4 * 8) = pk;
            }
        } else {
            #pragma unroll
            for (int j = 0; j < 2; ++j) {
                int u = j * 512 + tid, row = u >> 3, c4 = u & 7;
                float v[4];
                #pragma unroll
                for (int e = 0; e < 4; ++e) {
                    int k = c4 * 4 + e;
                    v[e] = (k < KWx) ? se[row + k] : 0.f;
                }
                uint2 pk;
                pk.x = packbf(v[0], v[1]);
                pk.y = packbf(v[2], v[3]);
                *(uint2*)(Ab + row * 80 + c4 * 8) = pk;
            }
        }

        CP_WAIT2();                              // B chunk c complete
        __syncthreads();                         // A+B visible; gates buffer reuse

        // prefetch next A chunk (c+1 < 16 from memory; chunk 16 built from se)
        if (c + 1 < 16) {
            #pragma unroll
            for (int j = 0; j < 2; ++j) {
                int u = j * 512 + tid, row = u >> 3, c4 = u & 7;
                aReg[j] = *(const float4*)&memb[(size_t)row * ENCx + (c + 1) * 32 + c4 * 4];
            }
        }
        if (c + 3 < NCH) copyB(c + 3, (c + 3) & 3);
        CP_COMMIT();                             // commit (possibly empty) every iter

        const uint32_t abase = smb + ABUF_OFF + abuf * ABUF_STRIDE;
        const uint32_t bst   = smb + BST_OFF + stage * BST_STRIDE;

        #pragma unroll
        for (int ks = 0; ks < 2; ++ks) {
            uint32_t a0[4], a1[4];
            LDSM_X4(a0, abase + (uint32_t)(wm * 32 + (lane & 15)) * 80
                        + ks * 32 + ((lane >> 4) << 4));
            LDSM_X4(a1, abase + (uint32_t)(wm * 32 + 16 + (lane & 15)) * 80
                        + ks * 32 + ((lane >> 4) << 4));
            #pragma unroll
            for (int p = 0; p < 4; ++p) {
                uint32_t bf[4];
                uint32_t baddr = bst + (uint32_t)(ks * 16 + (lane & 15)) * 528
                               + (uint32_t)(wn * 64 + p * 16 + ((lane >> 4) << 3)) * 2;
                LDSM_X4T(bf, baddr);
                MMA16816(acc[2 * p],         a0, bf[0], bf[1]);
                MMA16816(acc[2 * p + 1],     a0, bf[2], bf[3]);
                MMA16816(acc[8 + 2 * p],     a1, bf[0], bf[1]);
                MMA16816(acc[8 + 2 * p + 1], a1, bf[2], bf[3]);
            }
        }
    }

    // ---- epilogue: tanh (MUFU), v_a dot, per-row energy reduce ----
    #pragma unroll
    for (int mt = 0; mt < 2; ++mt) {
        float e0 = 0.f, e1 = 0.f;
        #pragma unroll
        for (int nt = 0; nt < 8; ++nt) {
            const float* cc = acc[mt * 8 + nt];
            int u0 = wn * 64 + nt * 8 + (lane & 3) * 2;
            e0 = fmaf(va_sm[u0],     tanh_fast(cc[0] + pq_sm[u0]),     e0);
            e0 = fmaf(va_sm[u0 + 1], tanh_fast(cc[1] + pq_sm[u0 + 1]), e0);
            e1 = fmaf(va_sm[u0],     tanh_fast(cc[2] + pq_sm[u0]),     e1);
            e1 = fmaf(va_sm[u0 + 1], tanh_fast(cc[3] + pq_sm[u0 + 1]), e1);
        }
        e0 += __shfl_xor_sync(0xffffffffu, e0, 1);
        e0 += __shfl_xor_sync(0xffffffffu, e0, 2);
        e1 += __shfl_xor_sync(0xffffffffu, e1, 1);
        e1 += __shfl_xor_sync(0xffffffffu, e1, 2);
        if ((lane & 3) == 0) {
            int row = wm * 32 + mt * 16 + (lane >> 2);
            e_red[wn * 128 + row]     = e0;
            e_red[wn * 128 + row + 8] = e1;
        }
    }
    __syncthreads();
    if (tid < BM) {
        float E = e_red[tid] + e_red[128 + tid] + e_red[256 + tid] + e_red[384 + tid];
        s_sm[tid] = 1.f / (1.f + __expf(-E));
    }
    __syncthreads();

    if (tid < 32) {
        float S  = s_sm[tid]  + s_sm[tid + 32]  + s_sm[tid + 64]  + s_sm[tid + 96];
        float St = st_sm[tid] + st_sm[tid + 32] + st_sm[tid + 64] + st_sm[tid + 96];
        #pragma unroll
        for (int off = 16; off > 0; off >>= 1) {
            S  += __shfl_xor_sync(0xffffffffu, S, off);
            St += __shfl_xor_sync(0xffffffffu, St, off);
        }
        if (tid == 0) {
            g_pS[b * NTILES + tile]  = S;
            g_pSt[b * NTILES + tile] = St;
        }
    }

    // ---- weighted memory column sums: 1 column per thread ----
    float aA = 0.f, aB = 0.f;
    const float* p = memb + tid;
    #pragma unroll 4
    for (int m = 0; m < BM; ++m) {
        float v = p[(size_t)m * ENCx];
        aA = fmaf(st_sm[m], v, aA);
        aB = fmaf(s_sm[m],  v, aB);
    }
    size_t base = (size_t)(b * NTILES + tile) * ENCx;
    g_pA[base + tid] = aA;
    g_pB[base + tid] = aB;
}

// ---------------- finalize: 512 threads, parallel reductions ----------------
__global__ __launch_bounds__(512)
void k_final(const float* __restrict__ Wm, const float* __restrict__ bm,
             float* __restrict__ out) {
    __shared__ float M[ENCx];
    __shared__ float sS[2];
    __shared__ float part[Ux];
    const int b = blockIdx.x, tid = threadIdx.x;   // 512 threads

    // parallel S/St reduction (warp 0, lanes 0-15 hold tiles)
    if (tid < 32) {
        float S  = (tid < NTILES) ? g_pS[b * NTILES + tid]  : 0.f;
        float St = (tid < NTILES) ? g_pSt[b * NTILES + tid] : 0.f;
        #pragma unroll
        for (int off = 8; off > 0; off >>= 1) {
            S  += __shfl_xor_sync(0xffffffffu, S, off);
            St += __shfl_xor_sync(0xffffffffu, St, off);
        }
        if (tid == 0) { sS[0] = S; sS[1] = St; }
    }

    // partial merge: one e-column per thread (512 = ENC)
    float a = 0.f, bb = 0.f;
    #pragma unroll
    for (int t = 0; t < NTILES; ++t) {
        a  += g_pA[(size_t)(b * NTILES + t) * ENCx + tid];
        bb += g_pB[(size_t)(b * NTILES + t) * ENCx + tid];
    }
    __syncthreads();
    M[tid] = a + bb * (1.f / sS[0]);
    __syncthreads();

    // GEMM: half = e-range, u = output column
    const int half = tid >> 8;
    const int u    = tid & 255;
    float acc = 0.f;
    #pragma unroll 1
    for (int e0 = half * 256; e0 < half * 256 + 256; e0 += 8) {
        float wv[8];
        #pragma unroll
        for (int j = 0; j < 8; ++j) wv[j] = Wm[(size_t)(e0 + j) * Ux + u];
        #pragma unroll
        for (int j = 0; j < 8; ++j) acc = fmaf(M[e0 + j], wv[j], acc);
    }
    if (half == 1) part[u] = acc;
    __syncthreads();
    if (half == 0) {
        float cumsum = sS[1] + 1.f;
        out[b * Ux + u] = fmaf(cumsum, bm[u], acc + part[u]);
    }
}

// ---------------- launch ----------------
extern "C" void kernel_launch(void* const* d_in, const int* in_sizes, int n_in,
                              void* d_out, int out_size) {
    const float* query  = (const float*)d_in[0];
    const float* state  = (const float*)d_in[1];
    const float* memory = (const float*)d_in[2];
    const float* Wq     = (const float*)d_in[3];
    const float* bq     = (const float*)d_in[4];
    const float* Wm     = (const float*)d_in[5];
    const float* bm     = (const float*)d_in[6];
    const float* Wl     = (const float*)d_in[7];
    const float* bl     = (const float*)d_in[8];
    const float* conv_w = (const float*)d_in[9];
    const float* conv_b = (const float*)d_in[10];
    const float* We     = (const float*)d_in[11];
    const float* be     = (const float*)d_in[12];
    const float* v_a    = (const float*)d_in[13];
    float* out = (float*)d_out;

    cudaFuncSetAttribute(k_main, cudaFuncAttributeMaxDynamicSharedMemorySize, SM_TOTAL);

    k_setup1<<<129, 256>>>(Wm, Wl, We, query, Wq, conv_w, conv_b);
    k_setup2<<<16, 256>>>(bq, bl, bm, We, be);
    k_main<<<Bx * NTILES, 512, SM_TOTAL>>>(memory, state, v_a);
    k_final<<<Bx, 512>>>(Wm, bm, out);
}